// round 1
// baseline (speedup 1.0000x reference)
#include <cuda_runtime.h>

#define B_TOT 16384
#define IN_D  64
#define N_R   128
#define OUT_D 32
#define W_COLS ((IN_D + 1) * N_R)   // 8320

// ---------------- device scratch (static: no allocations allowed) ----------
__device__ float g_S [IN_D * N_R];                 // scale[i][r]
__device__ float g_C2[IN_D * N_R];                 // 2*scale*center
__device__ float g_K0[N_R];                        // sum_i scale*center^2
__device__ float g_Wd[N_R * (IN_D + 1) * OUT_D * 2]; // [r][65][2*o] duplicated pairs

// ---------------- prep kernels ---------------------------------------------
__global__ void prep_tables(const float* __restrict__ centers,
                            const float* __restrict__ sigmas) {
    int r = threadIdx.x;            // 128 threads
    float k0 = 0.f;
    for (int i = 0; i < IN_D; ++i) {
        float sg = sigmas[i * N_R + r];
        float c  = centers[i * N_R + r];
        float s  = 0.5f / (sg * sg) + 1e-8f;     // H / sigma^2 + EPS
        g_S [i * N_R + r] = s;
        g_C2[i * N_R + r] = 2.f * s * c;
        k0 = fmaf(s * c, c, k0);
    }
    g_K0[r] = k0;
}

// Relayout W[o, r*64+i] -> g_Wd[r][i][2o] with each value duplicated so the
// main GEMM can consume (w,w) pairs directly with fma.rn.f32x2 (no pack movs).
// Row i==64 holds the rule-only column W[o, 8192+r] (virtual x==1 row).
__global__ void prep_w(const float* __restrict__ W) {
    const int tot = N_R * (IN_D + 1) * OUT_D;
    for (int idx = blockIdx.x * blockDim.x + threadIdx.x; idx < tot;
         idx += gridDim.x * blockDim.x) {
        int o = idx & 31;
        int i = (idx >> 5) % (IN_D + 1);
        int r = idx / ((IN_D + 1) * OUT_D);
        float v = (i < IN_D) ? W[o * W_COLS + r * IN_D + i]
                             : W[o * W_COLS + IN_D * N_R + r];
        int base = ((r * (IN_D + 1) + i) << 6) + (o << 1);
        g_Wd[base]     = v;
        g_Wd[base + 1] = v;
    }
}

// ---------------- kernel A: logits + softmax -> frs -------------------------
// block = 256 threads (8 warps), each warp owns 8 rows of X; lane owns 4 rules.
__global__ void __launch_bounds__(256) kernelA(const float* __restrict__ X,
                                               float* __restrict__ frs) {
    __shared__ float sX[64 * IN_D];
    int t = threadIdx.x;
    int bBase = blockIdx.x * 64;

    const float4* src = (const float4*)(X + (size_t)bBase * IN_D);
    float4* dst = (float4*)sX;
    for (int idx = t; idx < 64 * IN_D / 4; idx += 256) dst[idx] = src[idx];
    __syncthreads();

    int warp = t >> 5, lane = t & 31;
    int r0   = lane << 2;     // 4 rules per lane -> 128 rules per warp
    int bloc = warp << 3;     // 8 rows per warp

    float acc[8][4];
#pragma unroll
    for (int bb = 0; bb < 8; ++bb)
        acc[bb][0] = acc[bb][1] = acc[bb][2] = acc[bb][3] = 0.f;

#pragma unroll 4
    for (int i = 0; i < IN_D; ++i) {
        float4 s4 = *(const float4*)(g_S  + i * N_R + r0);
        float4 c4 = *(const float4*)(g_C2 + i * N_R + r0);
#pragma unroll
        for (int bb = 0; bb < 8; ++bb) {
            float x  = sX[(bloc + bb) * IN_D + i];
            float xx = x * x;
            acc[bb][0] = fmaf(x, c4.x, fmaf(-xx, s4.x, acc[bb][0]));
            acc[bb][1] = fmaf(x, c4.y, fmaf(-xx, s4.y, acc[bb][1]));
            acc[bb][2] = fmaf(x, c4.z, fmaf(-xx, s4.z, acc[bb][2]));
            acc[bb][3] = fmaf(x, c4.w, fmaf(-xx, s4.w, acc[bb][3]));
        }
    }

    float4 k0 = *(const float4*)(g_K0 + r0);
#pragma unroll
    for (int bb = 0; bb < 8; ++bb) {
        float l0 = acc[bb][0] - k0.x, l1 = acc[bb][1] - k0.y;
        float l2 = acc[bb][2] - k0.z, l3 = acc[bb][3] - k0.w;
        float m = fmaxf(fmaxf(l0, l1), fmaxf(l2, l3));
#pragma unroll
        for (int off = 16; off; off >>= 1)
            m = fmaxf(m, __shfl_xor_sync(0xffffffffu, m, off));
        float e0 = __expf(l0 - m), e1 = __expf(l1 - m);
        float e2 = __expf(l2 - m), e3 = __expf(l3 - m);
        float s = e0 + e1 + e2 + e3;
#pragma unroll
        for (int off = 16; off; off >>= 1)
            s += __shfl_xor_sync(0xffffffffu, s, off);
        float inv = 1.f / s;
        float4 o4 = make_float4(e0 * inv, e1 * inv, e2 * inv, e3 * inv);
        *(float4*)(frs + (size_t)(bBase + bloc + bb) * N_R + r0) = o4;
    }
}

// ---------------- kernel B: fused per-rule GEMM + contraction ---------------
typedef unsigned long long ull;
#define FFMA2(d, a, b) \
    asm("fma.rn.f32x2 %0, %1, %2, %0;" : "+l"(d) : "l"(a), "l"(b))

#define SMEM_B ((65 * 128 + 128 * 128 + 65 * 64) * 4)   // 115456 bytes

__global__ void __launch_bounds__(256) kernelB(const float* __restrict__ X,
                                               const float* __restrict__ frs,
                                               const float* __restrict__ bias,
                                               float* __restrict__ out) {
    extern __shared__ float sm[];
    float* sXT = sm;                   // [65][128]  (i-major, row 64 = ones)
    float* sFT = sm + 65 * 128;        // [128][128] (r-major)
    float* sW  = sFT + 128 * 128;      // [65][64]   duplicated pairs, per rule

    int t = threadIdx.x;
    int bBase = blockIdx.x * 128;

    if (t < 128) {
        const float4* xr = (const float4*)(X + (size_t)(bBase + t) * IN_D);
#pragma unroll
        for (int j = 0; j < 16; ++j) {
            float4 v = xr[j];
            sXT[(4 * j + 0) * 128 + t] = v.x;
            sXT[(4 * j + 1) * 128 + t] = v.y;
            sXT[(4 * j + 2) * 128 + t] = v.z;
            sXT[(4 * j + 3) * 128 + t] = v.w;
        }
        sXT[64 * 128 + t] = 1.0f;
        const float4* fr = (const float4*)(frs + (size_t)(bBase + t) * N_R);
#pragma unroll
        for (int j = 0; j < 32; ++j) {
            float4 v = fr[j];
            sFT[(4 * j + 0) * 128 + t] = v.x;
            sFT[(4 * j + 1) * 128 + t] = v.y;
            sFT[(4 * j + 2) * 128 + t] = v.z;
            sFT[(4 * j + 3) * 128 + t] = v.w;
        }
    }

    int og = t & 7, bg = t >> 3;
    int o0 = og << 2;          // 4 outputs per thread
    int b0 = bg << 2;          // 4 rows per thread = 2 f32x2 pairs

    ull acc[2][4] = {{0ull, 0ull, 0ull, 0ull}, {0ull, 0ull, 0ull, 0ull}};

    for (int r = 0; r < N_R; ++r) {
        __syncthreads();
        {   // stage W chunk for this rule: 65 x 64 floats (duplicated pairs)
            const float4* wsrc = (const float4*)(g_Wd + (size_t)r * 65 * 64);
            float4* wdst = (float4*)sW;
            for (int idx = t; idx < 65 * 64 / 4; idx += 256)
                wdst[idx] = wsrc[idx];
        }
        __syncthreads();

        ull e[2][4] = {{0ull, 0ull, 0ull, 0ull}, {0ull, 0ull, 0ull, 0ull}};
#pragma unroll
        for (int i = 0; i <= IN_D; ++i) {
            ulonglong2 xv = *(const ulonglong2*)(sXT + i * 128 + b0);
            ulonglong2 wa = *(const ulonglong2*)(sW + i * 64 + (o0 << 1));
            ulonglong2 wb = *(const ulonglong2*)(sW + i * 64 + (o0 << 1) + 4);
            FFMA2(e[0][0], xv.x, wa.x); FFMA2(e[0][1], xv.x, wa.y);
            FFMA2(e[0][2], xv.x, wb.x); FFMA2(e[0][3], xv.x, wb.y);
            FFMA2(e[1][0], xv.y, wa.x); FFMA2(e[1][1], xv.y, wa.y);
            FFMA2(e[1][2], xv.y, wb.x); FFMA2(e[1][3], xv.y, wb.y);
        }
        ull f0 = *(const ull*)(sFT + r * 128 + b0);
        ull f1 = *(const ull*)(sFT + r * 128 + b0 + 2);
        FFMA2(acc[0][0], f0, e[0][0]); FFMA2(acc[0][1], f0, e[0][1]);
        FFMA2(acc[0][2], f0, e[0][2]); FFMA2(acc[0][3], f0, e[0][3]);
        FFMA2(acc[1][0], f1, e[1][0]); FFMA2(acc[1][1], f1, e[1][1]);
        FFMA2(acc[1][2], f1, e[1][2]); FFMA2(acc[1][3], f1, e[1][3]);
    }

    float4 bo = *(const float4*)(bias + o0);
#pragma unroll
    for (int p = 0; p < 2; ++p) {
        float2 c0 = *(float2*)&acc[p][0];
        float2 c1 = *(float2*)&acc[p][1];
        float2 c2 = *(float2*)&acc[p][2];
        float2 c3 = *(float2*)&acc[p][3];
        float4 lo = make_float4(c0.x + bo.x, c1.x + bo.y, c2.x + bo.z, c3.x + bo.w);
        float4 hi = make_float4(c0.y + bo.x, c1.y + bo.y, c2.y + bo.z, c3.y + bo.w);
        *(float4*)(out + (size_t)(bBase + b0 + 2 * p)     * OUT_D + o0) = lo;
        *(float4*)(out + (size_t)(bBase + b0 + 2 * p + 1) * OUT_D + o0) = hi;
    }
}

// ---------------- launch ----------------------------------------------------
extern "C" void kernel_launch(void* const* d_in, const int* in_sizes, int n_in,
                              void* d_out, int out_size) {
    const float* X       = (const float*)d_in[0];
    const float* centers = (const float*)d_in[1];
    const float* sigmas  = (const float*)d_in[2];
    const float* W       = (const float*)d_in[3];
    const float* bias    = (const float*)d_in[4];

    float* out = (float*)d_out;                    // [16384, 32]
    float* frs = out + (size_t)B_TOT * OUT_D;      // [16384, 128]

    cudaFuncSetAttribute(kernelB, cudaFuncAttributeMaxDynamicSharedMemorySize,
                         SMEM_B);

    prep_tables<<<1, 128>>>(centers, sigmas);
    prep_w<<<512, 256>>>(W);
    kernelA<<<B_TOT / 64, 256>>>(X, frs);
    kernelB<<<B_TOT / 128, 256, SMEM_B>>>(X, frs, bias, out);
}

// round 3
// speedup vs baseline: 9.8221x; 9.8221x over previous
#include <cuda_runtime.h>
#include <cuda_bf16.h>
#include <cstdint>

#define B_TOT 16384
#define IN_D  64
#define N_R   128
#define OUT_D 32
#define W_COLS ((IN_D + 1) * N_R)   // 8320

#define N_CHUNK 32                  // rule chunks (4 rules -> N=128 per chunk)
#define RC 4

// ---------------- device scratch ---------------------------------------
__device__ float g_S [IN_D * N_R];
__device__ float g_C2[IN_D * N_R];
__device__ float g_K0[N_R];
__device__ unsigned int g_Bh[N_CHUNK * 4096];   // pre-swizzled bf16-hi W tiles
__device__ unsigned int g_Bl[N_CHUNK * 4096];   // pre-swizzled bf16-lo W tiles
__device__ float g_Wf[N_R * OUT_D];             // rule-bias column (fp32)

// ---------------- helpers ------------------------------------------------
#define SWZ(x) ((x) ^ (((x) >> 3) & 0x70))

__device__ __forceinline__ uint32_t smem_u32(const void* p) {
    uint32_t a;
    asm("{ .reg .u64 t; cvta.to.shared.u64 t, %1; cvt.u32.u64 %0, t; }"
        : "=r"(a) : "l"(p));
    return a;
}
__device__ __forceinline__ void cp16(uint32_t dst, const void* src) {
    uint64_t g;
    asm("cvta.to.global.u64 %0, %1;" : "=l"(g) : "l"(src));
    asm volatile("cp.async.cg.shared.global [%0], [%1], 16;"
                 :: "r"(dst), "l"(g) : "memory");
}
#define CP_COMMIT() asm volatile("cp.async.commit_group;" ::: "memory")
#define CP_WAIT0()  asm volatile("cp.async.wait_group 0;" ::: "memory")

#define LDSM4(r, a) \
    asm volatile("ldmatrix.sync.aligned.m8n8.x4.shared.b16 {%0,%1,%2,%3}, [%4];" \
        : "=r"((r)[0]), "=r"((r)[1]), "=r"((r)[2]), "=r"((r)[3]) : "r"(a))

#define MMA(d, a, b0, b1) \
    asm volatile("mma.sync.aligned.m16n8k16.row.col.f32.bf16.bf16.f32 " \
        "{%0,%1,%2,%3},{%4,%5,%6,%7},{%8,%9},{%0,%1,%2,%3};" \
        : "+f"((d)[0]), "+f"((d)[1]), "+f"((d)[2]), "+f"((d)[3]) \
        : "r"((a)[0]), "r"((a)[1]), "r"((a)[2]), "r"((a)[3]), \
          "r"(b0), "r"(b1))

__device__ __forceinline__ unsigned int pack_bf2(__nv_bfloat16 a, __nv_bfloat16 b) {
    return (unsigned int)__bfloat16_as_ushort(a)
         | ((unsigned int)__bfloat16_as_ushort(b) << 16);
}

// ---------------- prep kernels -------------------------------------------
__global__ void prep_tables(const float* __restrict__ centers,
                            const float* __restrict__ sigmas) {
    int r = threadIdx.x;
    float k0 = 0.f;
    for (int i = 0; i < IN_D; ++i) {
        float sg = sigmas[i * N_R + r];
        float c  = centers[i * N_R + r];
        float s  = 0.5f / (sg * sg) + 1e-8f;
        g_S [i * N_R + r] = s;
        g_C2[i * N_R + r] = 2.f * s * c;
        k0 = fmaf(s * c, c, k0);
    }
    g_K0[r] = k0;
}

// Build pre-swizzled bf16 hi/lo W tiles: chunk tile = [128 n][64 k], SW128.
// n = rc*32 + o  (4 rules x 32 outs per chunk).
__global__ void prep_wb(const float* __restrict__ W) {
    int idx = blockIdx.x * blockDim.x + threadIdx.x;
    if (idx < N_CHUNK * 4096) {
        int c   = idx >> 12;
        int rem = idx & 4095;       // byte_off = rem*4 = n*128 + k2*4
        int n   = rem >> 5, k2 = rem & 31;
        int rc  = n >> 5,   o  = n & 31;
        int r   = c * RC + rc;
        int k   = k2 * 2;
        float v0 = W[o * W_COLS + r * IN_D + k];
        float v1 = W[o * W_COLS + r * IN_D + k + 1];
        __nv_bfloat16 h0 = __float2bfloat16(v0), h1 = __float2bfloat16(v1);
        __nv_bfloat16 l0 = __float2bfloat16(v0 - __bfloat162float(h0));
        __nv_bfloat16 l1 = __float2bfloat16(v1 - __bfloat162float(h1));
        unsigned int sw = SWZ((unsigned)(rem * 4));
        g_Bh[c * 4096 + (sw >> 2)] = pack_bf2(h0, h1);
        g_Bl[c * 4096 + (sw >> 2)] = pack_bf2(l0, l1);
    } else if (idx < N_CHUNK * 4096 + N_R * OUT_D) {
        int j = idx - N_CHUNK * 4096;
        int r = j >> 5, o = j & 31;
        g_Wf[j] = W[o * W_COLS + IN_D * N_R + r];
    }
}

// ---------------- kernel A: logits + softmax -> frs ----------------------
__global__ void __launch_bounds__(256) kernelA(const float* __restrict__ X,
                                               float* __restrict__ frs) {
    __shared__ float sX[64 * IN_D];
    int t = threadIdx.x;
    int bBase = blockIdx.x * 64;

    const float4* src = (const float4*)(X + (size_t)bBase * IN_D);
    float4* dst = (float4*)sX;
    for (int idx = t; idx < 64 * IN_D / 4; idx += 256) dst[idx] = src[idx];
    __syncthreads();

    int warp = t >> 5, lane = t & 31;
    int r0   = lane << 2;
    int bloc = warp << 3;

    float acc[8][4];
#pragma unroll
    for (int bb = 0; bb < 8; ++bb)
        acc[bb][0] = acc[bb][1] = acc[bb][2] = acc[bb][3] = 0.f;

#pragma unroll 4
    for (int i = 0; i < IN_D; ++i) {
        float4 s4 = *(const float4*)(g_S  + i * N_R + r0);
        float4 c4 = *(const float4*)(g_C2 + i * N_R + r0);
#pragma unroll
        for (int bb = 0; bb < 8; ++bb) {
            float x  = sX[(bloc + bb) * IN_D + i];
            float xx = x * x;
            acc[bb][0] = fmaf(x, c4.x, fmaf(-xx, s4.x, acc[bb][0]));
            acc[bb][1] = fmaf(x, c4.y, fmaf(-xx, s4.y, acc[bb][1]));
            acc[bb][2] = fmaf(x, c4.z, fmaf(-xx, s4.z, acc[bb][2]));
            acc[bb][3] = fmaf(x, c4.w, fmaf(-xx, s4.w, acc[bb][3]));
        }
    }

    float4 k0 = *(const float4*)(g_K0 + r0);
#pragma unroll
    for (int bb = 0; bb < 8; ++bb) {
        float l0 = acc[bb][0] - k0.x, l1 = acc[bb][1] - k0.y;
        float l2 = acc[bb][2] - k0.z, l3 = acc[bb][3] - k0.w;
        float m = fmaxf(fmaxf(l0, l1), fmaxf(l2, l3));
#pragma unroll
        for (int off = 16; off; off >>= 1)
            m = fmaxf(m, __shfl_xor_sync(0xffffffffu, m, off));
        float e0 = __expf(l0 - m), e1 = __expf(l1 - m);
        float e2 = __expf(l2 - m), e3 = __expf(l3 - m);
        float s = e0 + e1 + e2 + e3;
#pragma unroll
        for (int off = 16; off; off >>= 1)
            s += __shfl_xor_sync(0xffffffffu, s, off);
        float inv = 1.f / s;
        float4 o4 = make_float4(e0 * inv, e1 * inv, e2 * inv, e3 * inv);
        *(float4*)(frs + (size_t)(bBase + bloc + bb) * N_R + r0) = o4;
    }
}

// ---------------- kernel B: HMMA fused GEMM + contraction ----------------
#define SM_AH 0
#define SM_AL 16384
#define SM_B  32768                 // 2 bufs x (hi 16K + lo 16K) = 64 KB
#define SM_WF 98304                 // 16 KB fp32 Wf[r][o]
#define SMEM_TOTAL 114688

__global__ void __launch_bounds__(256) kernelB_mma(const float* __restrict__ X,
                                                   const float* __restrict__ frs,
                                                   const float* __restrict__ bias,
                                                   float* __restrict__ out) {
    extern __shared__ __align__(1024) char smem[];
    uint32_t sb = smem_u32(smem);
    int tid = threadIdx.x;
    int wid = tid >> 5, lane = tid & 31;
    int bBase = blockIdx.x * 128;

    // A tiles: X rows -> bf16 hi/lo, SW128-swizzled [128 rows x 64 k]
    for (int idx = tid; idx < 2048; idx += 256) {
        int row = idx >> 4, q = idx & 15;
        float4 v = ((const float4*)(X + (size_t)(bBase + row) * IN_D))[q];
        __nv_bfloat16 h0 = __float2bfloat16(v.x), h1 = __float2bfloat16(v.y);
        __nv_bfloat16 h2 = __float2bfloat16(v.z), h3 = __float2bfloat16(v.w);
        __nv_bfloat16 l0 = __float2bfloat16(v.x - __bfloat162float(h0));
        __nv_bfloat16 l1 = __float2bfloat16(v.y - __bfloat162float(h1));
        __nv_bfloat16 l2 = __float2bfloat16(v.z - __bfloat162float(h2));
        __nv_bfloat16 l3 = __float2bfloat16(v.w - __bfloat162float(h3));
        unsigned int sw = SWZ((unsigned)(row * 128 + q * 8));
        *(uint2*)(smem + SM_AH + sw) = make_uint2(pack_bf2(h0, h1), pack_bf2(h2, h3));
        *(uint2*)(smem + SM_AL + sw) = make_uint2(pack_bf2(l0, l1), pack_bf2(l2, l3));
    }
    // Wf table
    for (int idx = tid; idx < N_R * OUT_D; idx += 256)
        ((float*)(smem + SM_WF))[idx] = g_Wf[idx];
    // stage B chunk 0 into buf 0
    for (int i = tid; i < 1024; i += 256) {
        cp16(sb + SM_B + i * 16,         (const char*)g_Bh + i * 16);
        cp16(sb + SM_B + 16384 + i * 16, (const char*)g_Bl + i * 16);
    }
    CP_COMMIT();
    CP_WAIT0();
    __syncthreads();

    float acc[2][4][2];
#pragma unroll
    for (int p = 0; p < 2; ++p)
#pragma unroll
        for (int q = 0; q < 4; ++q) acc[p][q][0] = acc[p][q][1] = 0.f;

    int mrow = (wid << 4) + (lane >> 2);           // warp-local row (lo)
    const float* wfs = (const float*)(smem + SM_WF);

    for (int c = 0; c < N_CHUNK; ++c) {
        int cur = c & 1, nxt = cur ^ 1;

        if (c + 1 < N_CHUNK) {
            const char* gh = (const char*)(g_Bh + (c + 1) * 4096);
            const char* gl = (const char*)(g_Bl + (c + 1) * 4096);
            uint32_t dh = sb + SM_B + nxt * 32768, dl = dh + 16384;
            for (int i = tid; i < 1024; i += 256) {
                cp16(dh + i * 16, gh + i * 16);
                cp16(dl + i * 16, gl + i * 16);
            }
        }
        CP_COMMIT();

        float4 f4lo = *(const float4*)(frs + (size_t)(bBase + mrow) * N_R + c * RC);
        float4 f4hi = *(const float4*)(frs + (size_t)(bBase + mrow + 8) * N_R + c * RC);

        // init accumulators with the rule-bias column Wf (fp32, exact)
        float d[16][4];
#pragma unroll
        for (int t = 0; t < 16; ++t) {
            int rr = c * RC + (t >> 2);
            int o0 = ((t & 3) << 3) + ((lane & 3) << 1);
            float2 wf = *(const float2*)(wfs + rr * OUT_D + o0);
            d[t][0] = wf.x; d[t][1] = wf.y; d[t][2] = wf.x; d[t][3] = wf.y;
        }

        uint32_t bufB = sb + SM_B + cur * 32768;
        int lrow = lane & 15, lcol = (lane >> 4) << 4;

#pragma unroll
        for (int ks = 0; ks < 4; ++ks) {
            int col = ks * 32 + lcol;
            uint32_t offA = SWZ((unsigned)(((wid << 4) + lrow) * 128 + col));
            uint32_t aH[4], aL[4];
            LDSM4(aH, sb + SM_AH + offA);
            LDSM4(aL, sb + SM_AL + offA);
#pragma unroll
            for (int tp = 0; tp < 8; ++tp) {
                uint32_t offB = SWZ((unsigned)((tp * 16 + lrow) * 128 + col));
                uint32_t bH[4], bL[4];
                LDSM4(bH, bufB + offB);
                LDSM4(bL, bufB + 16384 + offB);
                MMA(d[2 * tp],     aH, bH[0], bH[2]);
                MMA(d[2 * tp],     aH, bL[0], bL[2]);
                MMA(d[2 * tp],     aL, bH[0], bH[2]);
                MMA(d[2 * tp + 1], aH, bH[1], bH[3]);
                MMA(d[2 * tp + 1], aH, bL[1], bL[3]);
                MMA(d[2 * tp + 1], aL, bH[1], bH[3]);
            }
        }

        // contract with firing levels
#pragma unroll
        for (int t = 0; t < 16; ++t) {
            float fl = (&f4lo.x)[t >> 2], fh = (&f4hi.x)[t >> 2];
            int q = t & 3;
            acc[0][q][0] = fmaf(fl, d[t][0], acc[0][q][0]);
            acc[0][q][1] = fmaf(fl, d[t][1], acc[0][q][1]);
            acc[1][q][0] = fmaf(fh, d[t][2], acc[1][q][0]);
            acc[1][q][1] = fmaf(fh, d[t][3], acc[1][q][1]);
        }

        CP_WAIT0();
        __syncthreads();
    }

    // write output (+ bias)
    int ob = (lane & 3) << 1;
#pragma unroll
    for (int p = 0; p < 2; ++p) {
        size_t row = (size_t)(bBase + mrow + p * 8);
#pragma unroll
        for (int q = 0; q < 4; ++q) {
            int o = q * 8 + ob;
            float2 v = make_float2(acc[p][q][0] + bias[o],
                                   acc[p][q][1] + bias[o + 1]);
            *(float2*)(out + row * OUT_D + o) = v;
        }
    }
}

// ---------------- launch --------------------------------------------------
extern "C" void kernel_launch(void* const* d_in, const int* in_sizes, int n_in,
                              void* d_out, int out_size) {
    const float* X       = (const float*)d_in[0];
    const float* centers = (const float*)d_in[1];
    const float* sigmas  = (const float*)d_in[2];
    const float* W       = (const float*)d_in[3];
    const float* bias    = (const float*)d_in[4];

    float* out = (float*)d_out;
    float* frs = out + (size_t)B_TOT * OUT_D;

    cudaFuncSetAttribute(kernelB_mma, cudaFuncAttributeMaxDynamicSharedMemorySize,
                         SMEM_TOTAL);

    prep_tables<<<1, 128>>>(centers, sigmas);
    prep_wb<<<(N_CHUNK * 4096 + N_R * OUT_D + 255) / 256, 256>>>(W);
    kernelA<<<B_TOT / 64, 256>>>(X, frs);
    kernelB_mma<<<B_TOT / 128, 256, SMEM_TOTAL>>>(X, frs, bias, out);
}

// round 5
// speedup vs baseline: 11.5249x; 1.1734x over previous
#include <cuda_runtime.h>
#include <cuda_bf16.h>
#include <cstdint>

#define B_TOT 16384
#define IN_D  64
#define N_R   128
#define OUT_D 32
#define W_COLS ((IN_D + 1) * N_R)   // 8320

#define N_CHUNK 32
#define RC 4
#define M_CTA 64

typedef unsigned long long ull;

// ---------------- device scratch ---------------------------------------
__device__ float g_S [IN_D * N_R];              // NEGATED scale: -s[i][r]
__device__ float g_C2[IN_D * N_R];              // 2*s*c
__device__ float g_K0[N_R];                     // sum_i s*c^2
__device__ unsigned int g_Bh[N_CHUNK * 4096];   // pre-swizzled bf16-hi W tiles
__device__ unsigned int g_Bl[N_CHUNK * 4096];   // pre-swizzled bf16-lo W tiles
__device__ float g_Wf[N_R * OUT_D];             // rule-bias column (fp32)

// ---------------- helpers ------------------------------------------------
#define SWZ(x) ((x) ^ (((x) >> 3) & 0x70))

__device__ __forceinline__ uint32_t smem_u32(const void* p) {
    uint32_t a;
    asm("{ .reg .u64 t; cvta.to.shared.u64 t, %1; cvt.u32.u64 %0, t; }"
        : "=r"(a) : "l"(p));
    return a;
}
__device__ __forceinline__ void cp16(uint32_t dst, const void* src) {
    uint64_t g;
    asm("cvta.to.global.u64 %0, %1;" : "=l"(g) : "l"(src));
    asm volatile("cp.async.cg.shared.global [%0], [%1], 16;"
                 :: "r"(dst), "l"(g) : "memory");
}
#define CP_COMMIT() asm volatile("cp.async.commit_group;" ::: "memory")
#define CP_WAIT0()  asm volatile("cp.async.wait_group 0;" ::: "memory")

#define LDSM4(r, a) \
    asm volatile("ldmatrix.sync.aligned.m8n8.x4.shared.b16 {%0,%1,%2,%3}, [%4];" \
        : "=r"((r)[0]), "=r"((r)[1]), "=r"((r)[2]), "=r"((r)[3]) : "r"(a))

#define MMA(d, a, b0, b1) \
    asm volatile("mma.sync.aligned.m16n8k16.row.col.f32.bf16.bf16.f32 " \
        "{%0,%1,%2,%3},{%4,%5,%6,%7},{%8,%9},{%0,%1,%2,%3};" \
        : "+f"((d)[0]), "+f"((d)[1]), "+f"((d)[2]), "+f"((d)[3]) \
        : "r"((a)[0]), "r"((a)[1]), "r"((a)[2]), "r"((a)[3]), \
          "r"(b0), "r"(b1))

// packed fp32x2 fma: d = a*b + c
#define FFMA2_4(d, a, b, c) \
    asm("fma.rn.f32x2 %0, %1, %2, %3;" : "=l"(d) : "l"(a), "l"(b), "l"(c))
#define PACK2(p, x) \
    asm("mov.b64 %0, {%1,%1};" : "=l"(p) : "r"(__float_as_uint(x)))

__device__ __forceinline__ unsigned int pack_bf2(__nv_bfloat16 a, __nv_bfloat16 b) {
    return (unsigned int)__bfloat16_as_ushort(a)
         | ((unsigned int)__bfloat16_as_ushort(b) << 16);
}

// ---------------- prep kernels -------------------------------------------
__global__ void prep_tables(const float* __restrict__ centers,
                            const float* __restrict__ sigmas) {
    int r = threadIdx.x;
    float k0 = 0.f;
    for (int i = 0; i < IN_D; ++i) {
        float sg = sigmas[i * N_R + r];
        float c  = centers[i * N_R + r];
        float s  = 0.5f / (sg * sg) + 1e-8f;
        g_S [i * N_R + r] = -s;                 // negated
        g_C2[i * N_R + r] = 2.f * s * c;
        k0 = fmaf(s * c, c, k0);
    }
    g_K0[r] = k0;
}

__global__ void prep_wb(const float* __restrict__ W) {
    int idx = blockIdx.x * blockDim.x + threadIdx.x;
    if (idx < N_CHUNK * 4096) {
        int c   = idx >> 12;
        int rem = idx & 4095;       // byte_off = rem*4 = n*128 + k2*4
        int n   = rem >> 5, k2 = rem & 31;
        int rc  = n >> 5,   o  = n & 31;
        int r   = c * RC + rc;
        int k   = k2 * 2;
        float v0 = W[o * W_COLS + r * IN_D + k];
        float v1 = W[o * W_COLS + r * IN_D + k + 1];
        __nv_bfloat16 h0 = __float2bfloat16(v0), h1 = __float2bfloat16(v1);
        __nv_bfloat16 l0 = __float2bfloat16(v0 - __bfloat162float(h0));
        __nv_bfloat16 l1 = __float2bfloat16(v1 - __bfloat162float(h1));
        unsigned int sw = SWZ((unsigned)(rem * 4));
        g_Bh[c * 4096 + (sw >> 2)] = pack_bf2(h0, h1);
        g_Bl[c * 4096 + (sw >> 2)] = pack_bf2(l0, l1);
    } else if (idx < N_CHUNK * 4096 + N_R * OUT_D) {
        int j = idx - N_CHUNK * 4096;
        int r = j >> 5, o = j & 31;
        g_Wf[j] = W[o * W_COLS + IN_D * N_R + r];
    }
}

// ---------------- fused kernel -------------------------------------------
// smem map (bytes):
//  [0,8192)        A hi tiles  [64 rows x 128B swizzled]   (epilogue: reduction)
//  [8192,16384)    A lo tiles
//  [16384,81920)   phase1: S table (32K) + C2 table (32K)
//                  phase2+: B double buffers: buf*32768 (hi 16K, lo 16K)
//  [81920,98304)   phase1: X fp32 [64x64];  phase3+: Wf [128x32] fp32
//  [98304,98816)   K0 [128] fp32
#define SM_A    0
#define SM_B    16384
#define SM_TABS 16384
#define SM_TABC 49152
#define SM_R    81920
#define SM_K0   98304
#define SMEM_TOTAL 98816

__global__ void __launch_bounds__(128) kfused(const float* __restrict__ X,
                                              const float* __restrict__ bias,
                                              float* __restrict__ out,
                                              float* __restrict__ frs) {
    extern __shared__ __align__(1024) char smem[];
    uint32_t sb = smem_u32(smem);
    int tid = threadIdx.x, wid = tid >> 5, lane = tid & 31;
    int bBase = blockIdx.x * M_CTA;

    // ---- phase 1: X -> fp32 tile + bf16 hi/lo A tiles; tables via cp.async
    for (int idx = tid; idx < 1024; idx += 128) {
        int row = idx >> 4, q = idx & 15;
        float4 v = ((const float4*)(X + (size_t)(bBase + row) * IN_D))[q];
        *(float4*)(smem + SM_R + row * 256 + q * 16) = v;
        __nv_bfloat16 h0 = __float2bfloat16(v.x), h1 = __float2bfloat16(v.y);
        __nv_bfloat16 h2 = __float2bfloat16(v.z), h3 = __float2bfloat16(v.w);
        __nv_bfloat16 l0 = __float2bfloat16(v.x - __bfloat162float(h0));
        __nv_bfloat16 l1 = __float2bfloat16(v.y - __bfloat162float(h1));
        __nv_bfloat16 l2 = __float2bfloat16(v.z - __bfloat162float(h2));
        __nv_bfloat16 l3 = __float2bfloat16(v.w - __bfloat162float(h3));
        unsigned int sw = SWZ((unsigned)(row * 128 + q * 8));
        *(uint2*)(smem + SM_A + sw)        = make_uint2(pack_bf2(h0, h1), pack_bf2(h2, h3));
        *(uint2*)(smem + SM_A + 8192 + sw) = make_uint2(pack_bf2(l0, l1), pack_bf2(l2, l3));
    }
    for (int i = tid; i < 2048; i += 128) cp16(sb + SM_TABS + i * 16, (const char*)g_S  + i * 16);
    for (int i = tid; i < 2048; i += 128) cp16(sb + SM_TABC + i * 16, (const char*)g_C2 + i * 16);
    if (tid < 32) cp16(sb + SM_K0 + tid * 16, (const char*)g_K0 + tid * 16);
    CP_COMMIT(); CP_WAIT0();
    __syncthreads();

    // ---- phase 2: logits (fma.rn.f32x2) + softmax -> frs
    {
        int w16 = wid * 16;
        ull acc2[16][2];
#pragma unroll
        for (int rr = 0; rr < 16; ++rr) acc2[rr][0] = acc2[rr][1] = 0ull;
        const float* Rx = (const float*)(smem + SM_R);
#pragma unroll
        for (int ig = 0; ig < 16; ++ig) {
            float4 xq[16];
#pragma unroll
            for (int rr = 0; rr < 16; ++rr)
                xq[rr] = *(const float4*)(Rx + (w16 + rr) * 64 + ig * 4);
#pragma unroll
            for (int ii = 0; ii < 4; ++ii) {
                int i = ig * 4 + ii;
                ulonglong2 s2 = *(const ulonglong2*)(smem + SM_TABS + i * 512 + lane * 16);
                ulonglong2 c2 = *(const ulonglong2*)(smem + SM_TABC + i * 512 + lane * 16);
#pragma unroll
                for (int rr = 0; rr < 16; ++rr) {
                    float x = (&xq[rr].x)[ii];
                    ull px; PACK2(px, x);
                    ull t0, t1;
                    FFMA2_4(t0, px, s2.x, c2.x);       // c2 - s*x
                    FFMA2_4(t1, px, s2.y, c2.y);
                    FFMA2_4(acc2[rr][0], px, t0, acc2[rr][0]);
                    FFMA2_4(acc2[rr][1], px, t1, acc2[rr][1]);
                }
            }
        }
        float4 k4 = *(const float4*)(smem + SM_K0 + lane * 16);
#pragma unroll
        for (int rr = 0; rr < 16; ++rr) {
            float2 a0 = *(float2*)&acc2[rr][0];
            float2 a1 = *(float2*)&acc2[rr][1];
            float l0 = a0.x - k4.x, l1 = a0.y - k4.y;
            float l2 = a1.x - k4.z, l3 = a1.y - k4.w;
            float m = fmaxf(fmaxf(l0, l1), fmaxf(l2, l3));
#pragma unroll
            for (int off = 16; off; off >>= 1)
                m = fmaxf(m, __shfl_xor_sync(0xffffffffu, m, off));
            float e0 = __expf(l0 - m), e1 = __expf(l1 - m);
            float e2 = __expf(l2 - m), e3 = __expf(l3 - m);
            float s = e0 + e1 + e2 + e3;
#pragma unroll
            for (int off = 16; off; off >>= 1)
                s += __shfl_xor_sync(0xffffffffu, s, off);
            float inv = 1.f / s;
            *(float4*)(frs + (size_t)(bBase + w16 + rr) * N_R + lane * 4) =
                make_float4(e0 * inv, e1 * inv, e2 * inv, e3 * inv);
        }
    }
    __threadfence_block();
    __syncthreads();

    // ---- phase 3: Wf -> smem, B chunk0 -> buf0
    for (int i = tid; i < 1024; i += 128) cp16(sb + SM_R + i * 16, (const char*)g_Wf + i * 16);
    for (int i = tid; i < 1024; i += 128) {
        cp16(sb + SM_B + i * 16,         (const char*)g_Bh + i * 16);
        cp16(sb + SM_B + 16384 + i * 16, (const char*)g_Bl + i * 16);
    }
    CP_COMMIT(); CP_WAIT0();
    __syncthreads();

    // ---- main loop: warp grid 2m x 2n (m32 x n64); n-split reduced at end
    int mq = wid >> 1, nq = wid & 1;
    int rm = mq * 32, nb = nq * 64;
    int lrow = lane & 15, lcol = (lane >> 4) << 4;
    int oc = (lane & 3) << 1;

    float acc[4][4][2];
#pragma unroll
    for (int a = 0; a < 4; ++a)
#pragma unroll
        for (int b = 0; b < 4; ++b) acc[a][b][0] = acc[a][b][1] = 0.f;

    const float* wfs = (const float*)(smem + SM_R);

    for (int c = 0; c < N_CHUNK; ++c) {
        int cur = c & 1, nxt = cur ^ 1;

        if (c + 1 < N_CHUNK) {
            const char* gh = (const char*)(g_Bh + (c + 1) * 4096);
            const char* gl = (const char*)(g_Bl + (c + 1) * 4096);
            uint32_t dh = sb + SM_B + nxt * 32768, dl = dh + 16384;
            for (int i = tid; i < 1024; i += 128) {
                cp16(dh + i * 16, gh + i * 16);
                cp16(dl + i * 16, gl + i * 16);
            }
        }
        CP_COMMIT();

        // firing levels: this warp's 2 rules (nq*2, nq*2+1), 4 row-positions
        float2 f2[2][2];
#pragma unroll
        for (int mt = 0; mt < 2; ++mt)
#pragma unroll
            for (int h = 0; h < 2; ++h) {
                int row = rm + mt * 16 + (lane >> 2) + h * 8;
                f2[mt][h] = *(const float2*)(frs + (size_t)(bBase + row) * N_R
                                             + c * RC + nq * 2);
            }

        // init d with the rule-bias column (fp32 exact)
        float d[2][4][2][4];
#pragma unroll
        for (int tp = 0; tp < 4; ++tp)
#pragma unroll
            for (int n8 = 0; n8 < 2; ++n8) {
                int rule = tp >> 1;
                int o0 = ((tp & 1) << 4) + (n8 << 3) + oc;
                float2 wf = *(const float2*)(wfs + (c * RC + nq * 2 + rule) * OUT_D + o0);
#pragma unroll
                for (int mt = 0; mt < 2; ++mt) {
                    d[mt][tp][n8][0] = wf.x; d[mt][tp][n8][1] = wf.y;
                    d[mt][tp][n8][2] = wf.x; d[mt][tp][n8][3] = wf.y;
                }
            }

        uint32_t bufB = sb + SM_B + cur * 32768;
#pragma unroll
        for (int ks = 0; ks < 4; ++ks) {
            int col = ks * 32 + lcol;
            uint32_t aH[2][4], aL[2][4];
#pragma unroll
            for (int mt = 0; mt < 2; ++mt) {
                uint32_t offA = SWZ((unsigned)((rm + mt * 16 + lrow) * 128 + col));
                LDSM4(aH[mt], sb + SM_A + offA);
                LDSM4(aL[mt], sb + SM_A + 8192 + offA);
            }
#pragma unroll
            for (int tp = 0; tp < 4; ++tp) {
                uint32_t offB = SWZ((unsigned)((nb + tp * 16 + lrow) * 128 + col));
                uint32_t bH[4], bL[4];
                LDSM4(bH, bufB + offB);
                LDSM4(bL, bufB + 16384 + offB);
#pragma unroll
                for (int mt = 0; mt < 2; ++mt) {
                    MMA(d[mt][tp][0], aH[mt], bH[0], bH[2]);
                    MMA(d[mt][tp][0], aH[mt], bL[0], bL[2]);
                    MMA(d[mt][tp][0], aL[mt], bH[0], bH[2]);
                    MMA(d[mt][tp][1], aH[mt], bH[1], bH[3]);
                    MMA(d[mt][tp][1], aH[mt], bL[1], bL[3]);
                    MMA(d[mt][tp][1], aL[mt], bH[1], bH[3]);
                }
            }
        }

        // contract with firing levels
#pragma unroll
        for (int mt = 0; mt < 2; ++mt)
#pragma unroll
            for (int tp = 0; tp < 4; ++tp)
#pragma unroll
                for (int n8 = 0; n8 < 2; ++n8) {
                    int rq = tp >> 1;
                    int op = ((tp & 1) << 1) + n8;
#pragma unroll
                    for (int h = 0; h < 2; ++h) {
                        float fl = rq ? f2[mt][h].y : f2[mt][h].x;
                        acc[mt * 2 + h][op][0] = fmaf(fl, d[mt][tp][n8][2 * h],     acc[mt * 2 + h][op][0]);
                        acc[mt * 2 + h][op][1] = fmaf(fl, d[mt][tp][n8][2 * h + 1], acc[mt * 2 + h][op][1]);
                    }
                }

        CP_WAIT0();
        __syncthreads();
    }

    // ---- epilogue: reduce nq pair via smem (A region is dead), + bias, store
    float* red = (float*)smem;            // [64][32] fp32 = 8 KB
    if (nq == 1) {
#pragma unroll
        for (int mt = 0; mt < 2; ++mt)
#pragma unroll
            for (int h = 0; h < 2; ++h) {
                int row = rm + mt * 16 + (lane >> 2) + h * 8;
#pragma unroll
                for (int op = 0; op < 4; ++op)
                    *(float2*)(red + row * 32 + op * 8 + oc) =
                        make_float2(acc[mt * 2 + h][op][0], acc[mt * 2 + h][op][1]);
            }
    }
    __syncthreads();
    if (nq == 0) {
        float2 b2[4];
#pragma unroll
        for (int op = 0; op < 4; ++op)
            b2[op] = *(const float2*)(bias + op * 8 + oc);
#pragma unroll
        for (int mt = 0; mt < 2; ++mt)
#pragma unroll
            for (int h = 0; h < 2; ++h) {
                int row = rm + mt * 16 + (lane >> 2) + h * 8;
#pragma unroll
                for (int op = 0; op < 4; ++op) {
                    float2 r2 = *(const float2*)(red + row * 32 + op * 8 + oc);
                    float2 v = make_float2(acc[mt * 2 + h][op][0] + r2.x + b2[op].x,
                                           acc[mt * 2 + h][op][1] + r2.y + b2[op].y);
                    *(float2*)(out + (size_t)(bBase + row) * OUT_D + op * 8 + oc) = v;
                }
            }
    }
}

// ---------------- launch --------------------------------------------------
extern "C" void kernel_launch(void* const* d_in, const int* in_sizes, int n_in,
                              void* d_out, int out_size) {
    const float* X       = (const float*)d_in[0];
    const float* centers = (const float*)d_in[1];
    const float* sigmas  = (const float*)d_in[2];
    const float* W       = (const float*)d_in[3];
    const float* bias    = (const float*)d_in[4];

    float* out = (float*)d_out;
    float* frs = out + (size_t)B_TOT * OUT_D;

    cudaFuncSetAttribute(kfused, cudaFuncAttributeMaxDynamicSharedMemorySize,
                         SMEM_TOTAL);

    prep_tables<<<1, 128>>>(centers, sigmas);
    prep_wb<<<(N_CHUNK * 4096 + N_R * OUT_D + 255) / 256, 256>>>(W);
    kfused<<<B_TOT / M_CTA, 128, SMEM_TOTAL>>>(X, bias, out, frs);
}

// round 6
// speedup vs baseline: 16.3021x; 1.4145x over previous
#include <cuda_runtime.h>
#include <cuda_fp16.h>
#include <cstdint>

#define B_TOT 16384
#define IN_D  64
#define N_R   128
#define OUT_D 32
#define W_COLS ((IN_D + 1) * N_R)   // 8320

#define N_CHUNK 32
#define RC 4
#define M_CTA 64

typedef unsigned long long ull;

// ---------------- device scratch ---------------------------------------
__device__ float g_S [IN_D * N_R];              // NEGATED scale: -s[i][r]
__device__ float g_C2[IN_D * N_R];              // 2*s*c
__device__ float g_K0[N_R];                     // sum_i s*c^2
__device__ unsigned int g_Bf[N_CHUNK * 4096];   // pre-swizzled fp16 W tiles
__device__ float g_Wf[N_R * OUT_D];             // rule-bias column (fp32)

// ---------------- helpers ------------------------------------------------
#define SWZ(x) ((x) ^ (((x) >> 3) & 0x70))

__device__ __forceinline__ uint32_t smem_u32(const void* p) {
    uint32_t a;
    asm("{ .reg .u64 t; cvta.to.shared.u64 t, %1; cvt.u32.u64 %0, t; }"
        : "=r"(a) : "l"(p));
    return a;
}
__device__ __forceinline__ void cp16(uint32_t dst, const void* src) {
    uint64_t g;
    asm("cvta.to.global.u64 %0, %1;" : "=l"(g) : "l"(src));
    asm volatile("cp.async.cg.shared.global [%0], [%1], 16;"
                 :: "r"(dst), "l"(g) : "memory");
}
#define CP_COMMIT() asm volatile("cp.async.commit_group;" ::: "memory")
#define CP_WAIT0()  asm volatile("cp.async.wait_group 0;" ::: "memory")

#define LDSM4(r, a) \
    asm volatile("ldmatrix.sync.aligned.m8n8.x4.shared.b16 {%0,%1,%2,%3}, [%4];" \
        : "=r"((r)[0]), "=r"((r)[1]), "=r"((r)[2]), "=r"((r)[3]) : "r"(a))

#define MMA(d, a, b0, b1) \
    asm volatile("mma.sync.aligned.m16n8k16.row.col.f32.f16.f16.f32 " \
        "{%0,%1,%2,%3},{%4,%5,%6,%7},{%8,%9},{%0,%1,%2,%3};" \
        : "+f"((d)[0]), "+f"((d)[1]), "+f"((d)[2]), "+f"((d)[3]) \
        : "r"((a)[0]), "r"((a)[1]), "r"((a)[2]), "r"((a)[3]), \
          "r"(b0), "r"(b1))

// packed fp32x2 fma: d = a*b + c
#define FFMA2_4(d, a, b, c) \
    asm("fma.rn.f32x2 %0, %1, %2, %3;" : "=l"(d) : "l"(a), "l"(b), "l"(c))
#define PACK2(p, x) \
    asm("mov.b64 %0, {%1,%1};" : "=l"(p) : "r"(__float_as_uint(x)))

__device__ __forceinline__ unsigned int pack_h2(__half a, __half b) {
    return (unsigned int)__half_as_ushort(a)
         | ((unsigned int)__half_as_ushort(b) << 16);
}

// ---------------- merged prep kernel --------------------------------------
// blocks [0,512): W tiles -> fp16 swizzled; [512,528): Wf; [528,656): tables
__global__ void __launch_bounds__(256) prep_all(const float* __restrict__ W,
                                                const float* __restrict__ centers,
                                                const float* __restrict__ sigmas) {
    int b = blockIdx.x, tid = threadIdx.x;
    if (b < 512) {
        int idx = b * 256 + tid;            // uint index in [0, 131072)
        int c   = idx >> 12;
        int rem = idx & 4095;               // byte_off = rem*4 = n*128 + k2*4
        int n   = rem >> 5, k2 = rem & 31;
        int rc  = n >> 5,   o  = n & 31;
        int r   = c * RC + rc;
        int k   = k2 * 2;
        float v0 = W[o * W_COLS + r * IN_D + k];
        float v1 = W[o * W_COLS + r * IN_D + k + 1];
        unsigned int sw = SWZ((unsigned)(rem * 4));
        g_Bf[c * 4096 + (sw >> 2)] = pack_h2(__float2half_rn(v0), __float2half_rn(v1));
    } else if (b < 528) {
        int j = (b - 512) * 256 + tid;      // [0, 4096)
        int r = j >> 5, o = j & 31;
        g_Wf[j] = W[o * W_COLS + IN_D * N_R + r];
    } else {
        int r = b - 528;                    // one rule per block
        __shared__ float red[64];
        if (tid < 64) {
            int i = tid;
            float sg = sigmas[i * N_R + r];
            float c  = centers[i * N_R + r];
            float s  = 0.5f / (sg * sg) + 1e-8f;
            g_S [i * N_R + r] = -s;
            g_C2[i * N_R + r] = 2.f * s * c;
            red[i] = s * c * c;
        }
        __syncthreads();
        if (tid == 0) {
            float k0 = 0.f;
#pragma unroll
            for (int i = 0; i < 64; ++i) k0 += red[i];
            g_K0[r] = k0;
        }
    }
}

// ---------------- fused kernel -------------------------------------------
// smem map (bytes):
//  [0,16384)       A tiles: hi [0,8K), lo [8K,16K)       (epilogue: reduction)
//  [16384,81920)   phase1: S table (32K) + C2 table (32K)
//                  phase3+: B double buffers 2 x 16K (only [16384,49152) used)
//  [81920,98304)   phase1: X fp32 [64x64];  phase3+: Wf [128x32] fp32
//  [98304,98816)   K0 [128] fp32
#define SM_A    0
#define SM_B    16384
#define SM_TABS 16384
#define SM_TABC 49152
#define SM_R    81920
#define SM_K0   98304
#define SMEM_TOTAL 98816

__global__ void __launch_bounds__(128) kfused(const float* __restrict__ X,
                                              const float* __restrict__ bias,
                                              float* __restrict__ out,
                                              float* __restrict__ frs) {
    extern __shared__ __align__(1024) char smem[];
    uint32_t sb = smem_u32(smem);
    int tid = threadIdx.x, wid = tid >> 5, lane = tid & 31;
    int bBase = blockIdx.x * M_CTA;

    // ---- phase 1: X -> fp32 tile + fp16 hi/lo A tiles; tables via cp.async
    for (int idx = tid; idx < 1024; idx += 128) {
        int row = idx >> 4, q = idx & 15;
        float4 v = ((const float4*)(X + (size_t)(bBase + row) * IN_D))[q];
        *(float4*)(smem + SM_R + row * 256 + q * 16) = v;
        __half h0 = __float2half_rn(v.x), h1 = __float2half_rn(v.y);
        __half h2 = __float2half_rn(v.z), h3 = __float2half_rn(v.w);
        __half l0 = __float2half_rn(v.x - __half2float(h0));
        __half l1 = __float2half_rn(v.y - __half2float(h1));
        __half l2 = __float2half_rn(v.z - __half2float(h2));
        __half l3 = __float2half_rn(v.w - __half2float(h3));
        unsigned int sw = SWZ((unsigned)(row * 128 + q * 8));
        *(uint2*)(smem + SM_A + sw)        = make_uint2(pack_h2(h0, h1), pack_h2(h2, h3));
        *(uint2*)(smem + SM_A + 8192 + sw) = make_uint2(pack_h2(l0, l1), pack_h2(l2, l3));
    }
    for (int i = tid; i < 2048; i += 128) cp16(sb + SM_TABS + i * 16, (const char*)g_S  + i * 16);
    for (int i = tid; i < 2048; i += 128) cp16(sb + SM_TABC + i * 16, (const char*)g_C2 + i * 16);
    if (tid < 32) cp16(sb + SM_K0 + tid * 16, (const char*)g_K0 + tid * 16);
    CP_COMMIT(); CP_WAIT0();
    __syncthreads();

    // ---- phase 2: logits (fma.rn.f32x2) + softmax -> frs
    {
        int w16 = wid * 16;
        ull acc2[16][2];
#pragma unroll
        for (int rr = 0; rr < 16; ++rr) acc2[rr][0] = acc2[rr][1] = 0ull;
        const float* Rx = (const float*)(smem + SM_R);
#pragma unroll
        for (int ig = 0; ig < 16; ++ig) {
            float4 xq[16];
#pragma unroll
            for (int rr = 0; rr < 16; ++rr)
                xq[rr] = *(const float4*)(Rx + (w16 + rr) * 64 + ig * 4);
#pragma unroll
            for (int ii = 0; ii < 4; ++ii) {
                int i = ig * 4 + ii;
                ulonglong2 s2 = *(const ulonglong2*)(smem + SM_TABS + i * 512 + lane * 16);
                ulonglong2 c2 = *(const ulonglong2*)(smem + SM_TABC + i * 512 + lane * 16);
#pragma unroll
                for (int rr = 0; rr < 16; ++rr) {
                    float x = (&xq[rr].x)[ii];
                    ull px; PACK2(px, x);
                    ull t0, t1;
                    FFMA2_4(t0, px, s2.x, c2.x);       // c2 - s*x
                    FFMA2_4(t1, px, s2.y, c2.y);
                    FFMA2_4(acc2[rr][0], px, t0, acc2[rr][0]);
                    FFMA2_4(acc2[rr][1], px, t1, acc2[rr][1]);
                }
            }
        }
        float4 k4 = *(const float4*)(smem + SM_K0 + lane * 16);
#pragma unroll
        for (int rr = 0; rr < 16; ++rr) {
            float2 a0 = *(float2*)&acc2[rr][0];
            float2 a1 = *(float2*)&acc2[rr][1];
            float l0 = a0.x - k4.x, l1 = a0.y - k4.y;
            float l2 = a1.x - k4.z, l3 = a1.y - k4.w;
            float m = fmaxf(fmaxf(l0, l1), fmaxf(l2, l3));
#pragma unroll
            for (int off = 16; off; off >>= 1)
                m = fmaxf(m, __shfl_xor_sync(0xffffffffu, m, off));
            float e0 = __expf(l0 - m), e1 = __expf(l1 - m);
            float e2 = __expf(l2 - m), e3 = __expf(l3 - m);
            float s = e0 + e1 + e2 + e3;
#pragma unroll
            for (int off = 16; off; off >>= 1)
                s += __shfl_xor_sync(0xffffffffu, s, off);
            float inv = 1.f / s;
            *(float4*)(frs + (size_t)(bBase + w16 + rr) * N_R + lane * 4) =
                make_float4(e0 * inv, e1 * inv, e2 * inv, e3 * inv);
        }
    }
    __threadfence_block();
    __syncthreads();

    // ---- phase 3: Wf -> smem, B chunk0 -> buf0
    for (int i = tid; i < 1024; i += 128) cp16(sb + SM_R + i * 16, (const char*)g_Wf + i * 16);
    for (int i = tid; i < 1024; i += 128) cp16(sb + SM_B + i * 16, (const char*)g_Bf + i * 16);
    CP_COMMIT(); CP_WAIT0();
    __syncthreads();

    // ---- main loop: warp grid 2m x 2n (m32 x n64); n-split reduced at end
    int mq = wid >> 1, nq = wid & 1;
    int rm = mq * 32, nb = nq * 64;
    int lrow = lane & 15, lcol = (lane >> 4) << 4;
    int oc = (lane & 3) << 1;

    float acc[4][4][2];
#pragma unroll
    for (int a = 0; a < 4; ++a)
#pragma unroll
        for (int b = 0; b < 4; ++b) acc[a][b][0] = acc[a][b][1] = 0.f;

    const float* wfs = (const float*)(smem + SM_R);

    for (int c = 0; c < N_CHUNK; ++c) {
        int cur = c & 1, nxt = cur ^ 1;

        if (c + 1 < N_CHUNK) {
            const char* gsrc = (const char*)(g_Bf + (c + 1) * 4096);
            uint32_t dd = sb + SM_B + nxt * 16384;
            for (int i = tid; i < 1024; i += 128) cp16(dd + i * 16, gsrc + i * 16);
        }
        CP_COMMIT();

        // firing levels: this warp's 2 rules (nq*2, nq*2+1), 4 row-positions
        float2 f2[2][2];
#pragma unroll
        for (int mt = 0; mt < 2; ++mt)
#pragma unroll
            for (int h = 0; h < 2; ++h) {
                int row = rm + mt * 16 + (lane >> 2) + h * 8;
                f2[mt][h] = *(const float2*)(frs + (size_t)(bBase + row) * N_R
                                             + c * RC + nq * 2);
            }

        // init d with the rule-bias column (fp32 exact)
        float d[2][4][2][4];
#pragma unroll
        for (int tp = 0; tp < 4; ++tp)
#pragma unroll
            for (int n8 = 0; n8 < 2; ++n8) {
                int rule = tp >> 1;
                int o0 = ((tp & 1) << 4) + (n8 << 3) + oc;
                float2 wf = *(const float2*)(wfs + (c * RC + nq * 2 + rule) * OUT_D + o0);
#pragma unroll
                for (int mt = 0; mt < 2; ++mt) {
                    d[mt][tp][n8][0] = wf.x; d[mt][tp][n8][1] = wf.y;
                    d[mt][tp][n8][2] = wf.x; d[mt][tp][n8][3] = wf.y;
                }
            }

        uint32_t bufB = sb + SM_B + cur * 16384;
#pragma unroll
        for (int ks = 0; ks < 4; ++ks) {
            int col = ks * 32 + lcol;
            uint32_t aH[2][4], aL[2][4];
#pragma unroll
            for (int mt = 0; mt < 2; ++mt) {
                uint32_t offA = SWZ((unsigned)((rm + mt * 16 + lrow) * 128 + col));
                LDSM4(aH[mt], sb + SM_A + offA);
                LDSM4(aL[mt], sb + SM_A + 8192 + offA);
            }
#pragma unroll
            for (int tp = 0; tp < 4; ++tp) {
                uint32_t offB = SWZ((unsigned)((nb + tp * 16 + lrow) * 128 + col));
                uint32_t bH[4];
                LDSM4(bH, bufB + offB);
#pragma unroll
                for (int mt = 0; mt < 2; ++mt) {
                    MMA(d[mt][tp][0], aH[mt], bH[0], bH[2]);
                    MMA(d[mt][tp][0], aL[mt], bH[0], bH[2]);
                    MMA(d[mt][tp][1], aH[mt], bH[1], bH[3]);
                    MMA(d[mt][tp][1], aL[mt], bH[1], bH[3]);
                }
            }
        }

        // contract with firing levels
#pragma unroll
        for (int mt = 0; mt < 2; ++mt)
#pragma unroll
            for (int tp = 0; tp < 4; ++tp)
#pragma unroll
                for (int n8 = 0; n8 < 2; ++n8) {
                    int rq = tp >> 1;
                    int op = ((tp & 1) << 1) + n8;
#pragma unroll
                    for (int h = 0; h < 2; ++h) {
                        float fl = rq ? f2[mt][h].y : f2[mt][h].x;
                        acc[mt * 2 + h][op][0] = fmaf(fl, d[mt][tp][n8][2 * h],     acc[mt * 2 + h][op][0]);
                        acc[mt * 2 + h][op][1] = fmaf(fl, d[mt][tp][n8][2 * h + 1], acc[mt * 2 + h][op][1]);
                    }
                }

        CP_WAIT0();
        __syncthreads();
    }

    // ---- epilogue: reduce nq pair via smem (A region is dead), + bias, store
    float* red = (float*)smem;            // [64][32] fp32 = 8 KB
    if (nq == 1) {
#pragma unroll
        for (int mt = 0; mt < 2; ++mt)
#pragma unroll
            for (int h = 0; h < 2; ++h) {
                int row = rm + mt * 16 + (lane >> 2) + h * 8;
#pragma unroll
                for (int op = 0; op < 4; ++op)
                    *(float2*)(red + row * 32 + op * 8 + oc) =
                        make_float2(acc[mt * 2 + h][op][0], acc[mt * 2 + h][op][1]);
            }
    }
    __syncthreads();
    if (nq == 0) {
        float2 b2[4];
#pragma unroll
        for (int op = 0; op < 4; ++op)
            b2[op] = *(const float2*)(bias + op * 8 + oc);
#pragma unroll
        for (int mt = 0; mt < 2; ++mt)
#pragma unroll
            for (int h = 0; h < 2; ++h) {
                int row = rm + mt * 16 + (lane >> 2) + h * 8;
#pragma unroll
                for (int op = 0; op < 4; ++op) {
                    float2 r2 = *(const float2*)(red + row * 32 + op * 8 + oc);
                    float2 v = make_float2(acc[mt * 2 + h][op][0] + r2.x + b2[op].x,
                                           acc[mt * 2 + h][op][1] + r2.y + b2[op].y);
                    *(float2*)(out + (size_t)(bBase + row) * OUT_D + op * 8 + oc) = v;
                }
            }
    }
}

// ---------------- launch --------------------------------------------------
extern "C" void kernel_launch(void* const* d_in, const int* in_sizes, int n_in,
                              void* d_out, int out_size) {
    const float* X       = (const float*)d_in[0];
    const float* centers = (const float*)d_in[1];
    const float* sigmas  = (const float*)d_in[2];
    const float* W       = (const float*)d_in[3];
    const float* bias    = (const float*)d_in[4];

    float* out = (float*)d_out;
    float* frs = out + (size_t)B_TOT * OUT_D;

    cudaFuncSetAttribute(kfused, cudaFuncAttributeMaxDynamicSharedMemorySize,
                         SMEM_TOTAL);

    prep_all<<<656, 256>>>(W, centers, sigmas);
    kfused<<<B_TOT / M_CTA, 128, SMEM_TOTAL>>>(X, bias, out, frs);
}

// round 7
// speedup vs baseline: 22.0321x; 1.3515x over previous
#include <cuda_runtime.h>
#include <cuda_fp16.h>
#include <cstdint>

#define B_TOT 16384
#define IN_D  64
#define N_R   128
#define OUT_D 32
#define W_COLS ((IN_D + 1) * N_R)   // 8320

#define N_CHUNK 32
#define RC 4
#define M_CTA 64

typedef unsigned long long ull;

// ---------------- device scratch ---------------------------------------
__device__ float g_S [IN_D * N_R];              // NEGATED scale: -s[i][r]
__device__ float g_C2[IN_D * N_R];              // 2*s*c
__device__ float g_K0[N_R];                     // sum_i s*c^2
__device__ unsigned int g_Bf[N_CHUNK * 4096];   // pre-swizzled fp16 W tiles
__device__ float g_Wf[N_R * OUT_D];             // rule-bias column (fp32)

// ---------------- helpers ------------------------------------------------
#define SWZ(x) ((x) ^ (((x) >> 3) & 0x70))

__device__ __forceinline__ uint32_t smem_u32(const void* p) {
    uint32_t a;
    asm("{ .reg .u64 t; cvta.to.shared.u64 t, %1; cvt.u32.u64 %0, t; }"
        : "=r"(a) : "l"(p));
    return a;
}
__device__ __forceinline__ void cp16(uint32_t dst, const void* src) {
    uint64_t g;
    asm("cvta.to.global.u64 %0, %1;" : "=l"(g) : "l"(src));
    asm volatile("cp.async.cg.shared.global [%0], [%1], 16;"
                 :: "r"(dst), "l"(g) : "memory");
}
#define CP_COMMIT() asm volatile("cp.async.commit_group;" ::: "memory")
#define CP_WAIT0()  asm volatile("cp.async.wait_group 0;" ::: "memory")

#define LDSM4(r, a) \
    asm volatile("ldmatrix.sync.aligned.m8n8.x4.shared.b16 {%0,%1,%2,%3}, [%4];" \
        : "=r"((r)[0]), "=r"((r)[1]), "=r"((r)[2]), "=r"((r)[3]) : "r"(a))

#define MMA(d, a, b0, b1) \
    asm volatile("mma.sync.aligned.m16n8k16.row.col.f32.f16.f16.f32 " \
        "{%0,%1,%2,%3},{%4,%5,%6,%7},{%8,%9},{%0,%1,%2,%3};" \
        : "+f"((d)[0]), "+f"((d)[1]), "+f"((d)[2]), "+f"((d)[3]) \
        : "r"((a)[0]), "r"((a)[1]), "r"((a)[2]), "r"((a)[3]), \
          "r"(b0), "r"(b1))

// packed fp32x2 fma: d = a*b + c
#define FFMA2_4(d, a, b, c) \
    asm("fma.rn.f32x2 %0, %1, %2, %3;" : "=l"(d) : "l"(a), "l"(b), "l"(c))
#define PACK2(p, x) \
    asm("mov.b64 %0, {%1,%1};" : "=l"(p) : "r"(__float_as_uint(x)))

__device__ __forceinline__ unsigned int pack_h2(__half a, __half b) {
    return (unsigned int)__half_as_ushort(a)
         | ((unsigned int)__half_as_ushort(b) << 16);
}

// ---------------- merged prep kernel --------------------------------------
// blocks [0,512): W tiles -> fp16 swizzled; [512,528): Wf; [528,656): tables
__global__ void __launch_bounds__(256) prep_all(const float* __restrict__ W,
                                                const float* __restrict__ centers,
                                                const float* __restrict__ sigmas) {
    int b = blockIdx.x, tid = threadIdx.x;
    if (b < 512) {
        int idx = b * 256 + tid;            // uint index in [0, 131072)
        int c   = idx >> 12;
        int rem = idx & 4095;               // byte_off = rem*4 = n*128 + k2*4
        int n   = rem >> 5, k2 = rem & 31;
        int rc  = n >> 5,   o  = n & 31;
        int r   = c * RC + rc;
        int k   = k2 * 2;
        float v0 = W[o * W_COLS + r * IN_D + k];
        float v1 = W[o * W_COLS + r * IN_D + k + 1];
        unsigned int sw = SWZ((unsigned)(rem * 4));
        g_Bf[c * 4096 + (sw >> 2)] = pack_h2(__float2half_rn(v0), __float2half_rn(v1));
    } else if (b < 528) {
        int j = (b - 512) * 256 + tid;      // [0, 4096)
        int r = j >> 5, o = j & 31;
        g_Wf[j] = W[o * W_COLS + IN_D * N_R + r];
    } else {
        int r = b - 528;                    // one rule per block
        __shared__ float red[64];
        if (tid < 64) {
            int i = tid;
            float sg = sigmas[i * N_R + r];
            float c  = centers[i * N_R + r];
            float s  = 0.5f / (sg * sg) + 1e-8f;
            g_S [i * N_R + r] = -s;
            g_C2[i * N_R + r] = 2.f * s * c;
            red[i] = s * c * c;
        }
        __syncthreads();
        if (tid == 0) {
            float k0 = 0.f;
#pragma unroll
            for (int i = 0; i < 64; ++i) k0 += red[i];
            g_K0[r] = k0;
        }
    }
}

// ---------------- fused kernel -------------------------------------------
// smem map (bytes):
//  [0,8192)        A fp16 tile [64 rows x 128B swz]   (epilogue: reduction)
//  [8192,40960)    phase1-2: S table (32K);   phase3+: B bufs 2 x 16K
//  [40960,73728)   phase1-2: C2 table (32K);  phase2+: frs smem [64][128] f32
//  [73728,90112)   phase1-2: X fp32 [64x64];  phase3+: Wf [128x32] fp32
//  [90112,90624)   K0 [128] fp32
#define SM_A    0
#define SM_B    8192
#define SM_TABS 8192
#define SM_TABC 40960
#define SM_FR   40960
#define SM_R    73728
#define SM_K0   90112
#define SMEM_TOTAL 90624

__global__ void __launch_bounds__(128) kfused(const float* __restrict__ X,
                                              const float* __restrict__ bias,
                                              float* __restrict__ out,
                                              float* __restrict__ frs) {
    extern __shared__ __align__(1024) char smem[];
    uint32_t sb = smem_u32(smem);
    int tid = threadIdx.x, wid = tid >> 5, lane = tid & 31;
    int bBase = blockIdx.x * M_CTA;

    // ---- phase 1: X -> fp32 tile + fp16 A tile; tables via cp.async
    for (int idx = tid; idx < 1024; idx += 128) {
        int row = idx >> 4, q = idx & 15;
        float4 v = ((const float4*)(X + (size_t)(bBase + row) * IN_D))[q];
        *(float4*)(smem + SM_R + row * 256 + q * 16) = v;
        unsigned int sw = SWZ((unsigned)(row * 128 + q * 8));
        *(uint2*)(smem + SM_A + sw) =
            make_uint2(pack_h2(__float2half_rn(v.x), __float2half_rn(v.y)),
                       pack_h2(__float2half_rn(v.z), __float2half_rn(v.w)));
    }
    for (int i = tid; i < 2048; i += 128) cp16(sb + SM_TABS + i * 16, (const char*)g_S  + i * 16);
    for (int i = tid; i < 2048; i += 128) cp16(sb + SM_TABC + i * 16, (const char*)g_C2 + i * 16);
    if (tid < 32) cp16(sb + SM_K0 + tid * 16, (const char*)g_K0 + tid * 16);
    CP_COMMIT(); CP_WAIT0();
    __syncthreads();

    // ---- phase 2: logits (fma.rn.f32x2), sync, softmax -> frs (smem+gmem)
    {
        int w16 = wid * 16;
        ull acc2[16][2];
#pragma unroll
        for (int rr = 0; rr < 16; ++rr) acc2[rr][0] = acc2[rr][1] = 0ull;
        const float* Rx = (const float*)(smem + SM_R);
#pragma unroll
        for (int ig = 0; ig < 16; ++ig) {
            float4 xq[16];
#pragma unroll
            for (int rr = 0; rr < 16; ++rr)
                xq[rr] = *(const float4*)(Rx + (w16 + rr) * 64 + ig * 4);
#pragma unroll
            for (int ii = 0; ii < 4; ++ii) {
                int i = ig * 4 + ii;
                ulonglong2 s2 = *(const ulonglong2*)(smem + SM_TABS + i * 512 + lane * 16);
                ulonglong2 c2 = *(const ulonglong2*)(smem + SM_TABC + i * 512 + lane * 16);
#pragma unroll
                for (int rr = 0; rr < 16; ++rr) {
                    float x = (&xq[rr].x)[ii];
                    ull px; PACK2(px, x);
                    ull t0, t1;
                    FFMA2_4(t0, px, s2.x, c2.x);       // c2 - s*x
                    FFMA2_4(t1, px, s2.y, c2.y);
                    FFMA2_4(acc2[rr][0], px, t0, acc2[rr][0]);
                    FFMA2_4(acc2[rr][1], px, t1, acc2[rr][1]);
                }
            }
        }
        __syncthreads();    // all table reads done before frs overwrites C2
        float4 k4 = *(const float4*)(smem + SM_K0 + lane * 16);
        float* sFR = (float*)(smem + SM_FR);
#pragma unroll
        for (int rr = 0; rr < 16; ++rr) {
            float2 a0 = *(float2*)&acc2[rr][0];
            float2 a1 = *(float2*)&acc2[rr][1];
            float l0 = a0.x - k4.x, l1 = a0.y - k4.y;
            float l2 = a1.x - k4.z, l3 = a1.y - k4.w;
            float m = fmaxf(fmaxf(l0, l1), fmaxf(l2, l3));
#pragma unroll
            for (int off = 16; off; off >>= 1)
                m = fmaxf(m, __shfl_xor_sync(0xffffffffu, m, off));
            float e0 = __expf(l0 - m), e1 = __expf(l1 - m);
            float e2 = __expf(l2 - m), e3 = __expf(l3 - m);
            float s = e0 + e1 + e2 + e3;
#pragma unroll
            for (int off = 16; off; off >>= 1)
                s += __shfl_xor_sync(0xffffffffu, s, off);
            float inv = 1.f / s;
            float4 o4 = make_float4(e0 * inv, e1 * inv, e2 * inv, e3 * inv);
            *(float4*)(sFR + (w16 + rr) * N_R + lane * 4) = o4;
            *(float4*)(frs + (size_t)(bBase + w16 + rr) * N_R + lane * 4) = o4;
        }
    }
    __syncthreads();

    // ---- phase 3: Wf -> smem (X dead), B chunk0 -> buf0 (S table dead)
    for (int i = tid; i < 1024; i += 128) cp16(sb + SM_R + i * 16, (const char*)g_Wf + i * 16);
    for (int i = tid; i < 1024; i += 128) cp16(sb + SM_B + i * 16, (const char*)g_Bf + i * 16);
    CP_COMMIT(); CP_WAIT0();
    __syncthreads();

    // ---- hoist A fragments (loop-invariant across all 32 chunks)
    int mq = wid >> 1, nq = wid & 1;
    int rm = mq * 32, nb = nq * 64;
    int lrow = lane & 15, lcol = (lane >> 4) << 4;
    int oc = (lane & 3) << 1;

    uint32_t aF[2][4][4];
#pragma unroll
    for (int mt = 0; mt < 2; ++mt)
#pragma unroll
        for (int ks = 0; ks < 4; ++ks) {
            uint32_t offA = SWZ((unsigned)((rm + mt * 16 + lrow) * 128 + ks * 32 + lcol));
            LDSM4(aF[mt][ks], sb + SM_A + offA);
        }

    float acc[4][4][2];
#pragma unroll
    for (int a = 0; a < 4; ++a)
#pragma unroll
        for (int b = 0; b < 4; ++b) acc[a][b][0] = acc[a][b][1] = 0.f;

    const float* wfs = (const float*)(smem + SM_R);
    const float* sFR = (const float*)(smem + SM_FR);

    for (int c = 0; c < N_CHUNK; ++c) {
        int cur = c & 1, nxt = cur ^ 1;

        if (c + 1 < N_CHUNK) {
            const char* gsrc = (const char*)(g_Bf + (c + 1) * 4096);
            uint32_t dd = sb + SM_B + nxt * 16384;
            for (int i = tid; i < 1024; i += 128) cp16(dd + i * 16, gsrc + i * 16);
        }
        CP_COMMIT();

        // firing levels from smem: this warp's 2 rules, 4 row-positions
        float2 f2[2][2];
#pragma unroll
        for (int mt = 0; mt < 2; ++mt)
#pragma unroll
            for (int h = 0; h < 2; ++h) {
                int row = rm + mt * 16 + (lane >> 2) + h * 8;
                f2[mt][h] = *(const float2*)(sFR + row * N_R + c * RC + nq * 2);
            }

        // init d with the rule-bias column (fp32 exact)
        float d[2][4][2][4];
#pragma unroll
        for (int tp = 0; tp < 4; ++tp)
#pragma unroll
            for (int n8 = 0; n8 < 2; ++n8) {
                int rule = tp >> 1;
                int o0 = ((tp & 1) << 4) + (n8 << 3) + oc;
                float2 wf = *(const float2*)(wfs + (c * RC + nq * 2 + rule) * OUT_D + o0);
#pragma unroll
                for (int mt = 0; mt < 2; ++mt) {
                    d[mt][tp][n8][0] = wf.x; d[mt][tp][n8][1] = wf.y;
                    d[mt][tp][n8][2] = wf.x; d[mt][tp][n8][3] = wf.y;
                }
            }

        uint32_t bufB = sb + SM_B + cur * 16384;
#pragma unroll
        for (int ks = 0; ks < 4; ++ks) {
            int col = ks * 32 + lcol;
#pragma unroll
            for (int tp = 0; tp < 4; ++tp) {
                uint32_t offB = SWZ((unsigned)((nb + tp * 16 + lrow) * 128 + col));
                uint32_t bH[4];
                LDSM4(bH, bufB + offB);
#pragma unroll
                for (int mt = 0; mt < 2; ++mt) {
                    MMA(d[mt][tp][0], aF[mt][ks], bH[0], bH[2]);
                    MMA(d[mt][tp][1], aF[mt][ks], bH[1], bH[3]);
                }
            }
        }

        // contract with firing levels
#pragma unroll
        for (int mt = 0; mt < 2; ++mt)
#pragma unroll
            for (int tp = 0; tp < 4; ++tp)
#pragma unroll
                for (int n8 = 0; n8 < 2; ++n8) {
                    int rq = tp >> 1;
                    int op = ((tp & 1) << 1) + n8;
#pragma unroll
                    for (int h = 0; h < 2; ++h) {
                        float fl = rq ? f2[mt][h].y : f2[mt][h].x;
                        acc[mt * 2 + h][op][0] = fmaf(fl, d[mt][tp][n8][2 * h],     acc[mt * 2 + h][op][0]);
                        acc[mt * 2 + h][op][1] = fmaf(fl, d[mt][tp][n8][2 * h + 1], acc[mt * 2 + h][op][1]);
                    }
                }

        CP_WAIT0();
        __syncthreads();
    }

    // ---- epilogue: reduce nq pair via smem (A region dead), + bias, store
    float* red = (float*)smem;            // [64][32] fp32 = 8 KB
    if (nq == 1) {
#pragma unroll
        for (int mt = 0; mt < 2; ++mt)
#pragma unroll
            for (int h = 0; h < 2; ++h) {
                int row = rm + mt * 16 + (lane >> 2) + h * 8;
#pragma unroll
                for (int op = 0; op < 4; ++op)
                    *(float2*)(red + row * 32 + op * 8 + oc) =
                        make_float2(acc[mt * 2 + h][op][0], acc[mt * 2 + h][op][1]);
            }
    }
    __syncthreads();
    if (nq == 0) {
        float2 b2[4];
#pragma unroll
        for (int op = 0; op < 4; ++op)
            b2[op] = *(const float2*)(bias + op * 8 + oc);
#pragma unroll
        for (int mt = 0; mt < 2; ++mt)
#pragma unroll
            for (int h = 0; h < 2; ++h) {
                int row = rm + mt * 16 + (lane >> 2) + h * 8;
#pragma unroll
                for (int op = 0; op < 4; ++op) {
                    float2 r2 = *(const float2*)(red + row * 32 + op * 8 + oc);
                    float2 v = make_float2(acc[mt * 2 + h][op][0] + r2.x + b2[op].x,
                                           acc[mt * 2 + h][op][1] + r2.y + b2[op].y);
                    *(float2*)(out + (size_t)(bBase + row) * OUT_D + op * 8 + oc) = v;
                }
            }
    }
}

// ---------------- launch --------------------------------------------------
extern "C" void kernel_launch(void* const* d_in, const int* in_sizes, int n_in,
                              void* d_out, int out_size) {
    const float* X       = (const float*)d_in[0];
    const float* centers = (const float*)d_in[1];
    const float* sigmas  = (const float*)d_in[2];
    const float* W       = (const float*)d_in[3];
    const float* bias    = (const float*)d_in[4];

    float* out = (float*)d_out;
    float* frs = out + (size_t)B_TOT * OUT_D;

    cudaFuncSetAttribute(kfused, cudaFuncAttributeMaxDynamicSharedMemorySize,
                         SMEM_TOTAL);

    prep_all<<<656, 256>>>(W, centers, sigmas);
    kfused<<<B_TOT / M_CTA, 128, SMEM_TOTAL>>>(X, bias, out, frs);
}

// round 8
// speedup vs baseline: 25.8226x; 1.1720x over previous
#include <cuda_runtime.h>
#include <cuda_fp16.h>
#include <cstdint>

#define B_TOT 16384
#define IN_D  64
#define N_R   128
#define OUT_D 32
#define W_COLS ((IN_D + 1) * N_R)   // 8320

#define N_CHUNK 32
#define RC 4
#define M_CTA 64

typedef unsigned long long ull;

// ---------------- device scratch ---------------------------------------
__device__ float g_K0[N_R];                     // sum_i s*c^2
__device__ unsigned int g_Bf[N_CHUNK * 4096];   // pre-swizzled fp16 W tiles
__device__ unsigned int g_LT[8 * 2048];         // logits tables: 8 stages x 8KB
                                                // stage s = tau*2+h, tau in
                                                // {sh, sl, c2h, c2l}, h = rule half
__device__ float g_Wf[N_R * OUT_D];             // rule-bias column (fp32)

// ---------------- helpers ------------------------------------------------
#define SWZ(x) ((x) ^ (((x) >> 3) & 0x70))

__device__ __forceinline__ uint32_t smem_u32(const void* p) {
    uint32_t a;
    asm("{ .reg .u64 t; cvta.to.shared.u64 t, %1; cvt.u32.u64 %0, t; }"
        : "=r"(a) : "l"(p));
    return a;
}
__device__ __forceinline__ void cp16(uint32_t dst, const void* src) {
    uint64_t g;
    asm("cvta.to.global.u64 %0, %1;" : "=l"(g) : "l"(src));
    asm volatile("cp.async.cg.shared.global [%0], [%1], 16;"
                 :: "r"(dst), "l"(g) : "memory");
}
#define CP_COMMIT() asm volatile("cp.async.commit_group;" ::: "memory")
#define CP_WAIT0()  asm volatile("cp.async.wait_group 0;" ::: "memory")
#define CP_WAIT1()  asm volatile("cp.async.wait_group 1;" ::: "memory")

#define LDSM4(r, a) \
    asm volatile("ldmatrix.sync.aligned.m8n8.x4.shared.b16 {%0,%1,%2,%3}, [%4];" \
        : "=r"((r)[0]), "=r"((r)[1]), "=r"((r)[2]), "=r"((r)[3]) : "r"(a))

#define MMA(d, a, b0, b1) \
    asm volatile("mma.sync.aligned.m16n8k16.row.col.f32.f16.f16.f32 " \
        "{%0,%1,%2,%3},{%4,%5,%6,%7},{%8,%9},{%0,%1,%2,%3};" \
        : "+f"((d)[0]), "+f"((d)[1]), "+f"((d)[2]), "+f"((d)[3]) \
        : "r"((a)[0]), "r"((a)[1]), "r"((a)[2]), "r"((a)[3]), \
          "r"(b0), "r"(b1))

__device__ __forceinline__ unsigned int pack_h2(__half a, __half b) {
    return (unsigned int)__half_as_ushort(a)
         | ((unsigned int)__half_as_ushort(b) << 16);
}

// ---------------- merged prep kernel --------------------------------------
// blocks [0,512): W tiles; [512,528): Wf; [528,592): logits tables; [592,720): k0
__global__ void __launch_bounds__(256) prep_all(const float* __restrict__ W,
                                                const float* __restrict__ centers,
                                                const float* __restrict__ sigmas) {
    int b = blockIdx.x, tid = threadIdx.x;
    if (b < 512) {
        int idx = b * 256 + tid;            // uint index in [0, 131072)
        int c   = idx >> 12;
        int rem = idx & 4095;               // byte_off = rem*4 = n*128 + k2*4
        int n   = rem >> 5, k2 = rem & 31;
        int rc  = n >> 5,   o  = n & 31;
        int r   = c * RC + rc;
        int k   = k2 * 2;
        float v0 = W[o * W_COLS + r * IN_D + k];
        float v1 = W[o * W_COLS + r * IN_D + k + 1];
        unsigned int sw = SWZ((unsigned)(rem * 4));
        g_Bf[c * 4096 + (sw >> 2)] = pack_h2(__float2half_rn(v0), __float2half_rn(v1));
    } else if (b < 528) {
        int j = (b - 512) * 256 + tid;      // [0, 4096)
        int r = j >> 5, o = j & 31;
        g_Wf[j] = W[o * W_COLS + IN_D * N_R + r];
    } else if (b < 592) {
        int idx = (b - 528) * 256 + tid;    // [0, 16384)
        int s   = idx >> 11;                // stage
        int rem = idx & 2047;               // byte = rem*4 = rr*128 + k2*4
        int rr  = rem >> 5, k2 = rem & 31;
        int tau = s >> 1,  h  = s & 1;
        int r   = h * 64 + rr;
        __half vv[2];
#pragma unroll
        for (int e = 0; e < 2; ++e) {
            int i = k2 * 2 + e;
            float sg = sigmas[i * N_R + r];
            float c  = centers[i * N_R + r];
            float s_ = 0.5f / (sg * sg) + 1e-8f;
            float c2 = 2.f * s_ * c;
            if (tau == 0)      vv[e] = __float2half_rn(-s_);
            else if (tau == 1) {
                __half vh = __float2half_rn(-s_);
                vv[e] = __float2half_rn(-s_ - __half2float(vh));
            } else if (tau == 2) vv[e] = __float2half_rn(c2);
            else {
                __half vh = __float2half_rn(c2);
                vv[e] = __float2half_rn(c2 - __half2float(vh));
            }
        }
        g_LT[s * 2048 + (SWZ((unsigned)(rem * 4)) >> 2)] = pack_h2(vv[0], vv[1]);
    } else {
        int r = b - 592;                    // one rule per block
        __shared__ float red[64];
        if (tid < 64) {
            int i = tid;
            float sg = sigmas[i * N_R + r];
            float c  = centers[i * N_R + r];
            float s_ = 0.5f / (sg * sg) + 1e-8f;
            red[i] = s_ * c * c;
        }
        __syncthreads();
        if (tid == 0) {
            float k0 = 0.f;
#pragma unroll
            for (int i = 0; i < 64; ++i) k0 += red[i];
            g_K0[r] = k0;
        }
    }
}

// ---------------- fused kernel -------------------------------------------
// smem map (bytes):
//  [0,8192)        T_xh: x fp16 tile (A for main GEMM too); epilogue: red
//  [8192,16384)    T_qh (x^2 hi)      ── after logits ──┐
//  [16384,24576)   T_ql (x^2 lo)                        ├ frs fp32 [64][128]
//  [24576,32768)   T_xl (x lo)                          │ = [8192, 40960)
//  [32768,40960)   (frs tail)                          ─┘
//  [40960,73728)   B double buffer 2x16K; logits stages use [57344..73728) 2x8K
//  [73728,90112)   Wf fp32 [128][32]
//  [90112,90624)   K0 [128] fp32
#define SM_XH 0
#define SM_QH 8192
#define SM_QL 16384
#define SM_XL 24576
#define SM_FR 8192
#define SM_B  40960
#define SM_LS 57344
#define SM_WF 73728
#define SM_K0 90112
#define SMEM_TOTAL 90624

__global__ void __launch_bounds__(128) kfused(const float* __restrict__ X,
                                              const float* __restrict__ bias,
                                              float* __restrict__ out,
                                              float* __restrict__ frs) {
    extern __shared__ __align__(1024) char smem[];
    uint32_t sb = smem_u32(smem);
    int tid = threadIdx.x, wid = tid >> 5, lane = tid & 31;
    int bBase = blockIdx.x * M_CTA;

    int lrow = lane & 15, lcol = (lane >> 4) << 4;
    int oc = (lane & 3) << 1;
    int w16 = wid << 4;

    // ---- phase 1: stage0 cp.async; build feature tiles from X
    for (int i = tid; i < 512; i += 128)
        cp16(sb + SM_LS + i * 16, (const char*)g_LT + i * 16);
    CP_COMMIT();

    for (int idx = tid; idx < 1024; idx += 128) {
        int row = idx >> 4, q = idx & 15;
        float4 v = ((const float4*)(X + (size_t)(bBase + row) * IN_D))[q];
        __half xh[4], xl[4], qh[4], ql[4];
#pragma unroll
        for (int e = 0; e < 4; ++e) {
            float x = (&v.x)[e];
            xh[e] = __float2half_rn(x);
            xl[e] = __float2half_rn(x - __half2float(xh[e]));
            float qf = x * x;
            qh[e] = __float2half_rn(qf);
            ql[e] = __float2half_rn(qf - __half2float(qh[e]));
        }
        unsigned int sw = SWZ((unsigned)(row * 128 + q * 8));
        *(uint2*)(smem + SM_XH + sw) = make_uint2(pack_h2(xh[0], xh[1]), pack_h2(xh[2], xh[3]));
        *(uint2*)(smem + SM_XL + sw) = make_uint2(pack_h2(xl[0], xl[1]), pack_h2(xl[2], xl[3]));
        *(uint2*)(smem + SM_QH + sw) = make_uint2(pack_h2(qh[0], qh[1]), pack_h2(qh[2], qh[3]));
        *(uint2*)(smem + SM_QL + sw) = make_uint2(pack_h2(ql[0], ql[1]), pack_h2(ql[2], ql[3]));
    }

    // ---- phase 2: logits via tensor cores, 8 pipelined table stages
    float dl[16][4];
#pragma unroll
    for (int t = 0; t < 16; ++t)
        dl[t][0] = dl[t][1] = dl[t][2] = dl[t][3] = 0.f;

#pragma unroll
    for (int j = 0; j < 8; ++j) {
        if (j < 7) {
            uint32_t dd = sb + SM_LS + ((j + 1) & 1) * 8192;
            const char* g = (const char*)g_LT + (j + 1) * 8192;
            for (int i = tid; i < 512; i += 128) cp16(dd + i * 16, g + i * 16);
        } else {
            // final stage: prefetch Wf, main-B chunk0, k0
            for (int i = tid; i < 1024; i += 128) cp16(sb + SM_WF + i * 16, (const char*)g_Wf + i * 16);
            for (int i = tid; i < 1024; i += 128) cp16(sb + SM_B + i * 16, (const char*)g_Bf + i * 16);
            if (tid < 32) cp16(sb + SM_K0 + tid * 16, (const char*)g_K0 + tid * 16);
        }
        CP_COMMIT();
        CP_WAIT1();                 // stage j has landed
        __syncthreads();

        const int tau = j >> 1, h = j & 1;
        const int np = (tau == 0 || tau == 2) ? 2 : 1;
        const uint32_t p0 = (tau < 2) ? SM_QH : SM_XH;
        const uint32_t p1 = (tau == 0) ? SM_QL : SM_XL;
        uint32_t bufS = sb + SM_LS + (j & 1) * 8192;

#pragma unroll
        for (int ks = 0; ks < 4; ++ks) {
            int col = ks * 32 + lcol;
            uint32_t bF[4][4];
#pragma unroll
            for (int jj = 0; jj < 4; ++jj)
                LDSM4(bF[jj], bufS + SWZ((unsigned)((jj * 16 + lrow) * 128 + col)));
            uint32_t aFr[4];
            LDSM4(aFr, sb + p0 + SWZ((unsigned)((w16 + lrow) * 128 + col)));
#pragma unroll
            for (int jj = 0; jj < 4; ++jj) {
                MMA(dl[h * 8 + 2 * jj],     aFr, bF[jj][0], bF[jj][2]);
                MMA(dl[h * 8 + 2 * jj + 1], aFr, bF[jj][1], bF[jj][3]);
            }
            if (np == 2) {
                uint32_t aF2[4];
                LDSM4(aF2, sb + p1 + SWZ((unsigned)((w16 + lrow) * 128 + col)));
#pragma unroll
                for (int jj = 0; jj < 4; ++jj) {
                    MMA(dl[h * 8 + 2 * jj],     aF2, bF[jj][0], bF[jj][2]);
                    MMA(dl[h * 8 + 2 * jj + 1], aF2, bF[jj][1], bF[jj][3]);
                }
            }
        }
        __syncthreads();
    }
    CP_WAIT0();                     // Wf, chunk0, k0 landed
    __syncthreads();

    // ---- phase 3: softmax on fragments -> frs (smem fp32 + gmem)
    {
        const float* k0p = (const float*)(smem + SM_K0);
        float mlo = -1e30f, mhi = -1e30f;
#pragma unroll
        for (int t = 0; t < 16; ++t) {
            float2 k2 = *(const float2*)(k0p + t * 8 + oc);
            dl[t][0] -= k2.x; dl[t][1] -= k2.y;
            dl[t][2] -= k2.x; dl[t][3] -= k2.y;
            mlo = fmaxf(mlo, fmaxf(dl[t][0], dl[t][1]));
            mhi = fmaxf(mhi, fmaxf(dl[t][2], dl[t][3]));
        }
#pragma unroll
        for (int off = 1; off < 4; off <<= 1) {
            mlo = fmaxf(mlo, __shfl_xor_sync(0xffffffffu, mlo, off));
            mhi = fmaxf(mhi, __shfl_xor_sync(0xffffffffu, mhi, off));
        }
        float slo = 0.f, shi = 0.f;
#pragma unroll
        for (int t = 0; t < 16; ++t) {
            dl[t][0] = __expf(dl[t][0] - mlo); dl[t][1] = __expf(dl[t][1] - mlo);
            dl[t][2] = __expf(dl[t][2] - mhi); dl[t][3] = __expf(dl[t][3] - mhi);
            slo += dl[t][0] + dl[t][1];
            shi += dl[t][2] + dl[t][3];
        }
#pragma unroll
        for (int off = 1; off < 4; off <<= 1) {
            slo += __shfl_xor_sync(0xffffffffu, slo, off);
            shi += __shfl_xor_sync(0xffffffffu, shi, off);
        }
        float ilo = 1.f / slo, ihi = 1.f / shi;
        int rlo = w16 + (lane >> 2), rhi = rlo + 8;
        float* sFR = (float*)(smem + SM_FR);
#pragma unroll
        for (int t = 0; t < 16; ++t) {
            float2 flo = make_float2(dl[t][0] * ilo, dl[t][1] * ilo);
            float2 fhi = make_float2(dl[t][2] * ihi, dl[t][3] * ihi);
            *(float2*)(sFR + rlo * N_R + t * 8 + oc) = flo;
            *(float2*)(sFR + rhi * N_R + t * 8 + oc) = fhi;
            *(float2*)(frs + (size_t)(bBase + rlo) * N_R + t * 8 + oc) = flo;
            *(float2*)(frs + (size_t)(bBase + rhi) * N_R + t * 8 + oc) = fhi;
        }
    }
    __syncthreads();

    // ---- main loop: warp grid 2m x 2n (m32 x n64); n-split reduced at end
    int mq = wid >> 1, nq = wid & 1;
    int rm = mq * 32, nb = nq * 64;

    // hoisted A fragments (T_xh) and B swizzle offsets
    uint32_t aF[2][4][4];
#pragma unroll
    for (int mt = 0; mt < 2; ++mt)
#pragma unroll
        for (int ks = 0; ks < 4; ++ks) {
            uint32_t offA = SWZ((unsigned)((rm + mt * 16 + lrow) * 128 + ks * 32 + lcol));
            LDSM4(aF[mt][ks], sb + SM_XH + offA);
        }
    uint32_t offB16[16];
#pragma unroll
    for (int ks = 0; ks < 4; ++ks)
#pragma unroll
        for (int tp = 0; tp < 4; ++tp)
            offB16[ks * 4 + tp] =
                SWZ((unsigned)((nb + tp * 16 + lrow) * 128 + ks * 32 + lcol));

    float acc[4][4][2];
#pragma unroll
    for (int a = 0; a < 4; ++a)
#pragma unroll
        for (int b = 0; b < 4; ++b) acc[a][b][0] = acc[a][b][1] = 0.f;

    const float* wfs = (const float*)(smem + SM_WF);
    const float* sFR = (const float*)(smem + SM_FR);

    for (int c = 0; c < N_CHUNK; ++c) {
        int cur = c & 1, nxt = cur ^ 1;

        if (c + 1 < N_CHUNK) {
            const char* gsrc = (const char*)(g_Bf + (c + 1) * 4096);
            uint32_t dd = sb + SM_B + nxt * 16384;
            for (int i = tid; i < 1024; i += 128) cp16(dd + i * 16, gsrc + i * 16);
        }
        CP_COMMIT();

        float2 f2[2][2];
#pragma unroll
        for (int mt = 0; mt < 2; ++mt)
#pragma unroll
            for (int h = 0; h < 2; ++h) {
                int row = rm + mt * 16 + (lane >> 2) + h * 8;
                f2[mt][h] = *(const float2*)(sFR + row * N_R + c * RC + nq * 2);
            }

        float d[2][4][2][4];
#pragma unroll
        for (int tp = 0; tp < 4; ++tp)
#pragma unroll
            for (int n8 = 0; n8 < 2; ++n8) {
                int rule = tp >> 1;
                int o0 = ((tp & 1) << 4) + (n8 << 3) + oc;
                float2 wf = *(const float2*)(wfs + (c * RC + nq * 2 + rule) * OUT_D + o0);
#pragma unroll
                for (int mt = 0; mt < 2; ++mt) {
                    d[mt][tp][n8][0] = wf.x; d[mt][tp][n8][1] = wf.y;
                    d[mt][tp][n8][2] = wf.x; d[mt][tp][n8][3] = wf.y;
                }
            }

        uint32_t bufB = sb + SM_B + cur * 16384;
#pragma unroll
        for (int ks = 0; ks < 4; ++ks) {
#pragma unroll
            for (int tp = 0; tp < 4; ++tp) {
                uint32_t bH[4];
                LDSM4(bH, bufB + offB16[ks * 4 + tp]);
#pragma unroll
                for (int mt = 0; mt < 2; ++mt) {
                    MMA(d[mt][tp][0], aF[mt][ks], bH[0], bH[2]);
                    MMA(d[mt][tp][1], aF[mt][ks], bH[1], bH[3]);
                }
            }
        }

#pragma unroll
        for (int mt = 0; mt < 2; ++mt)
#pragma unroll
            for (int tp = 0; tp < 4; ++tp)
#pragma unroll
                for (int n8 = 0; n8 < 2; ++n8) {
                    int rq = tp >> 1;
                    int op = ((tp & 1) << 1) + n8;
#pragma unroll
                    for (int h = 0; h < 2; ++h) {
                        float fl = rq ? f2[mt][h].y : f2[mt][h].x;
                        acc[mt * 2 + h][op][0] = fmaf(fl, d[mt][tp][n8][2 * h],     acc[mt * 2 + h][op][0]);
                        acc[mt * 2 + h][op][1] = fmaf(fl, d[mt][tp][n8][2 * h + 1], acc[mt * 2 + h][op][1]);
                    }
                }

        CP_WAIT0();
        __syncthreads();
    }

    // ---- epilogue: reduce nq pair via smem (T_xh region dead), + bias, store
    float* red = (float*)smem;            // [64][32] fp32 = 8 KB
    if (nq == 1) {
#pragma unroll
        for (int mt = 0; mt < 2; ++mt)
#pragma unroll
            for (int h = 0; h < 2; ++h) {
                int row = rm + mt * 16 + (lane >> 2) + h * 8;
#pragma unroll
                for (int op = 0; op < 4; ++op)
                    *(float2*)(red + row * 32 + op * 8 + oc) =
                        make_float2(acc[mt * 2 + h][op][0], acc[mt * 2 + h][op][1]);
            }
    }
    __syncthreads();
    if (nq == 0) {
        float2 b2[4];
#pragma unroll
        for (int op = 0; op < 4; ++op)
            b2[op] = *(const float2*)(bias + op * 8 + oc);
#pragma unroll
        for (int mt = 0; mt < 2; ++mt)
#pragma unroll
            for (int h = 0; h < 2; ++h) {
                int row = rm + mt * 16 + (lane >> 2) + h * 8;
#pragma unroll
                for (int op = 0; op < 4; ++op) {
                    float2 r2 = *(const float2*)(red + row * 32 + op * 8 + oc);
                    float2 v = make_float2(acc[mt * 2 + h][op][0] + r2.x + b2[op].x,
                                           acc[mt * 2 + h][op][1] + r2.y + b2[op].y);
                    *(float2*)(out + (size_t)(bBase + row) * OUT_D + op * 8 + oc) = v;
                }
            }
    }
}

// ---------------- launch --------------------------------------------------
extern "C" void kernel_launch(void* const* d_in, const int* in_sizes, int n_in,
                              void* d_out, int out_size) {
    const float* X       = (const float*)d_in[0];
    const float* centers = (const float*)d_in[1];
    const float* sigmas  = (const float*)d_in[2];
    const float* W       = (const float*)d_in[3];
    const float* bias    = (const float*)d_in[4];

    float* out = (float*)d_out;
    float* frs = out + (size_t)B_TOT * OUT_D;

    cudaFuncSetAttribute(kfused, cudaFuncAttributeMaxDynamicSharedMemorySize,
                         SMEM_TOTAL);

    prep_all<<<720, 256>>>(W, centers, sigmas);
    kfused<<<B_TOT / M_CTA, 128, SMEM_TOTAL>>>(X, bias, out, frs);
}

// round 9
// speedup vs baseline: 25.8399x; 1.0007x over previous
#include <cuda_runtime.h>
#include <cuda_fp16.h>
#include <cstdint>

#define B_TOT 16384
#define IN_D  64
#define N_R   128
#define OUT_D 32
#define W_COLS ((IN_D + 1) * N_R)   // 8320

#define N_CHUNK 32
#define RC 4
#define M_CTA 64

typedef unsigned long long ull;

// ---------------- device scratch ---------------------------------------
__device__ float g_K0[N_R];                     // sum_i s*c^2
__device__ unsigned int g_Bf[N_CHUNK * 4096];   // pre-swizzled fp16 W tiles
__device__ unsigned int g_LT[8 * 2048];         // logits tables: 8 stages x 8KB
__device__ float g_Wf[N_R * OUT_D];             // rule-bias column (fp32)

// ---------------- helpers ------------------------------------------------
#define SWZ(x) ((x) ^ (((x) >> 3) & 0x70))

__device__ __forceinline__ uint32_t smem_u32(const void* p) {
    uint32_t a;
    asm("{ .reg .u64 t; cvta.to.shared.u64 t, %1; cvt.u32.u64 %0, t; }"
        : "=r"(a) : "l"(p));
    return a;
}
__device__ __forceinline__ void cp16(uint32_t dst, const void* src) {
    uint64_t g;
    asm("cvta.to.global.u64 %0, %1;" : "=l"(g) : "l"(src));
    asm volatile("cp.async.cg.shared.global [%0], [%1], 16;"
                 :: "r"(dst), "l"(g) : "memory");
}
#define CP_COMMIT() asm volatile("cp.async.commit_group;" ::: "memory")
#define CP_WAIT0()  asm volatile("cp.async.wait_group 0;" ::: "memory")
#define CP_WAIT1()  asm volatile("cp.async.wait_group 1;" ::: "memory")
#define BAR_PAIR(id) asm volatile("bar.sync %0, 64;" :: "r"(id) : "memory")

#define LDSM4(r, a) \
    asm volatile("ldmatrix.sync.aligned.m8n8.x4.shared.b16 {%0,%1,%2,%3}, [%4];" \
        : "=r"((r)[0]), "=r"((r)[1]), "=r"((r)[2]), "=r"((r)[3]) : "r"(a))

#define MMA(d, a, b0, b1) \
    asm volatile("mma.sync.aligned.m16n8k16.row.col.f32.f16.f16.f32 " \
        "{%0,%1,%2,%3},{%4,%5,%6,%7},{%8,%9},{%0,%1,%2,%3};" \
        : "+f"((d)[0]), "+f"((d)[1]), "+f"((d)[2]), "+f"((d)[3]) \
        : "r"((a)[0]), "r"((a)[1]), "r"((a)[2]), "r"((a)[3]), \
          "r"(b0), "r"(b1))

__device__ __forceinline__ unsigned int pack_h2(__half a, __half b) {
    return (unsigned int)__half_as_ushort(a)
         | ((unsigned int)__half_as_ushort(b) << 16);
}

// ---------------- merged prep kernel --------------------------------------
// blocks [0,512): W tiles; [512,528): Wf; [528,592): logits tables; [592,720): k0
__global__ void __launch_bounds__(256) prep_all(const float* __restrict__ W,
                                                const float* __restrict__ centers,
                                                const float* __restrict__ sigmas) {
    int b = blockIdx.x, tid = threadIdx.x;
    if (b < 512) {
        int idx = b * 256 + tid;            // uint index in [0, 131072)
        int c   = idx >> 12;
        int rem = idx & 4095;               // byte_off = rem*4 = n*128 + k2*4
        int n   = rem >> 5, k2 = rem & 31;
        int rc  = n >> 5,   o  = n & 31;
        int r   = c * RC + rc;
        int k   = k2 * 2;
        float v0 = W[o * W_COLS + r * IN_D + k];
        float v1 = W[o * W_COLS + r * IN_D + k + 1];
        unsigned int sw = SWZ((unsigned)(rem * 4));
        g_Bf[c * 4096 + (sw >> 2)] = pack_h2(__float2half_rn(v0), __float2half_rn(v1));
    } else if (b < 528) {
        int j = (b - 512) * 256 + tid;      // [0, 4096)
        int r = j >> 5, o = j & 31;
        g_Wf[j] = W[o * W_COLS + IN_D * N_R + r];
    } else if (b < 592) {
        int idx = (b - 528) * 256 + tid;    // [0, 16384)
        int s   = idx >> 11;                // stage
        int rem = idx & 2047;               // byte = rem*4 = rr*128 + k2*4
        int rr  = rem >> 5, k2 = rem & 31;
        int tau = s >> 1,  h  = s & 1;
        int r   = h * 64 + rr;
        __half vv[2];
#pragma unroll
        for (int e = 0; e < 2; ++e) {
            int i = k2 * 2 + e;
            float sg = sigmas[i * N_R + r];
            float c  = centers[i * N_R + r];
            float s_ = 0.5f / (sg * sg) + 1e-8f;
            float c2 = 2.f * s_ * c;
            if (tau == 0)      vv[e] = __float2half_rn(-s_);
            else if (tau == 1) {
                __half vh = __float2half_rn(-s_);
                vv[e] = __float2half_rn(-s_ - __half2float(vh));
            } else if (tau == 2) vv[e] = __float2half_rn(c2);
            else {
                __half vh = __float2half_rn(c2);
                vv[e] = __float2half_rn(c2 - __half2float(vh));
            }
        }
        g_LT[s * 2048 + (SWZ((unsigned)(rem * 4)) >> 2)] = pack_h2(vv[0], vv[1]);
    } else {
        int r = b - 592;                    // one rule per block
        __shared__ float red[64];
        if (tid < 64) {
            int i = tid;
            float sg = sigmas[i * N_R + r];
            float c  = centers[i * N_R + r];
            float s_ = 0.5f / (sg * sg) + 1e-8f;
            red[i] = s_ * c * c;
        }
        __syncthreads();
        if (tid == 0) {
            float k0 = 0.f;
#pragma unroll
            for (int i = 0; i < 64; ++i) k0 += red[i];
            g_K0[r] = k0;
        }
    }
}

// ---------------- fused kernel -------------------------------------------
// smem map (bytes):
//  [0,8192)        T_xh: x fp16 tile (A for main GEMM too); epilogue: red
//  [8192,16384)    T_qh   ── after logits: frs fp32 [64][128] = [8192,40960)
//  [16384,24576)   T_ql
//  [24576,32768)   T_xl
//  [40960,73728)   B: 4 x 8KB regions [nq][buf]; logits stages use [57344..) 2x8K
//  [73728,90112)   Wf fp32 [128][32]
//  [90112,90624)   K0 [128] fp32
#define SM_XH 0
#define SM_QH 8192
#define SM_QL 16384
#define SM_XL 24576
#define SM_FR 8192
#define SM_B  40960
#define SM_LS 57344
#define SM_WF 73728
#define SM_K0 90112
#define SMEM_TOTAL 90624

__global__ void __launch_bounds__(128) kfused(const float* __restrict__ X,
                                              const float* __restrict__ bias,
                                              float* __restrict__ out,
                                              float* __restrict__ frs) {
    extern __shared__ __align__(1024) char smem[];
    uint32_t sb = smem_u32(smem);
    int tid = threadIdx.x, wid = tid >> 5, lane = tid & 31;
    int bBase = blockIdx.x * M_CTA;

    int lrow = lane & 15, lcol = (lane >> 4) << 4;
    int oc = (lane & 3) << 1;
    int w16 = wid << 4;

    // ---- phase 1: stage0 cp.async; build feature tiles from X
    for (int i = tid; i < 512; i += 128)
        cp16(sb + SM_LS + i * 16, (const char*)g_LT + i * 16);
    CP_COMMIT();

    for (int idx = tid; idx < 1024; idx += 128) {
        int row = idx >> 4, q = idx & 15;
        float4 v = ((const float4*)(X + (size_t)(bBase + row) * IN_D))[q];
        __half xh[4], xl[4], qh[4], ql[4];
#pragma unroll
        for (int e = 0; e < 4; ++e) {
            float x = (&v.x)[e];
            xh[e] = __float2half_rn(x);
            xl[e] = __float2half_rn(x - __half2float(xh[e]));
            float qf = x * x;
            qh[e] = __float2half_rn(qf);
            ql[e] = __float2half_rn(qf - __half2float(qh[e]));
        }
        unsigned int sw = SWZ((unsigned)(row * 128 + q * 8));
        *(uint2*)(smem + SM_XH + sw) = make_uint2(pack_h2(xh[0], xh[1]), pack_h2(xh[2], xh[3]));
        *(uint2*)(smem + SM_XL + sw) = make_uint2(pack_h2(xl[0], xl[1]), pack_h2(xl[2], xl[3]));
        *(uint2*)(smem + SM_QH + sw) = make_uint2(pack_h2(qh[0], qh[1]), pack_h2(qh[2], qh[3]));
        *(uint2*)(smem + SM_QL + sw) = make_uint2(pack_h2(ql[0], ql[1]), pack_h2(ql[2], ql[3]));
    }

    // ---- phase 2: logits via tensor cores, 8 pipelined table stages
    float dl[16][4];
#pragma unroll
    for (int t = 0; t < 16; ++t)
        dl[t][0] = dl[t][1] = dl[t][2] = dl[t][3] = 0.f;

#pragma unroll
    for (int j = 0; j < 8; ++j) {
        if (j < 7) {
            uint32_t dd = sb + SM_LS + ((j + 1) & 1) * 8192;
            const char* g = (const char*)g_LT + (j + 1) * 8192;
            for (int i = tid; i < 512; i += 128) cp16(dd + i * 16, g + i * 16);
        } else {
            // final stage: prefetch Wf, main-B chunk0 (into [nq][0] regions), k0
            for (int i = tid; i < 1024; i += 128) cp16(sb + SM_WF + i * 16, (const char*)g_Wf + i * 16);
            for (int i = tid; i < 1024; i += 128) {
                int nqh = i >> 9;           // which half of chunk0
                int off = i & 511;
                cp16(sb + SM_B + nqh * 16384 + off * 16,
                     (const char*)g_Bf + nqh * 8192 + off * 16);
            }
            if (tid < 32) cp16(sb + SM_K0 + tid * 16, (const char*)g_K0 + tid * 16);
        }
        CP_COMMIT();
        CP_WAIT1();                 // stage j has landed
        __syncthreads();

        const int tau = j >> 1, h = j & 1;
        const int np = (tau == 0 || tau == 2) ? 2 : 1;
        const uint32_t p0 = (tau < 2) ? SM_QH : SM_XH;
        const uint32_t p1 = (tau == 0) ? SM_QL : SM_XL;
        uint32_t bufS = sb + SM_LS + (j & 1) * 8192;

#pragma unroll
        for (int ks = 0; ks < 4; ++ks) {
            int col = ks * 32 + lcol;
            uint32_t bF[4][4];
#pragma unroll
            for (int jj = 0; jj < 4; ++jj)
                LDSM4(bF[jj], bufS + SWZ((unsigned)((jj * 16 + lrow) * 128 + col)));
            uint32_t aFr[4];
            LDSM4(aFr, sb + p0 + SWZ((unsigned)((w16 + lrow) * 128 + col)));
#pragma unroll
            for (int jj = 0; jj < 4; ++jj) {
                MMA(dl[h * 8 + 2 * jj],     aFr, bF[jj][0], bF[jj][2]);
                MMA(dl[h * 8 + 2 * jj + 1], aFr, bF[jj][1], bF[jj][3]);
            }
            if (np == 2) {
                uint32_t aF2[4];
                LDSM4(aF2, sb + p1 + SWZ((unsigned)((w16 + lrow) * 128 + col)));
#pragma unroll
                for (int jj = 0; jj < 4; ++jj) {
                    MMA(dl[h * 8 + 2 * jj],     aF2, bF[jj][0], bF[jj][2]);
                    MMA(dl[h * 8 + 2 * jj + 1], aF2, bF[jj][1], bF[jj][3]);
                }
            }
        }
        __syncthreads();
    }
    CP_WAIT0();                     // Wf, chunk0, k0 landed
    __syncthreads();

    // ---- phase 3: softmax on fragments -> frs (smem fp32 + gmem)
    {
        const float* k0p = (const float*)(smem + SM_K0);
        float mlo = -1e30f, mhi = -1e30f;
#pragma unroll
        for (int t = 0; t < 16; ++t) {
            float2 k2 = *(const float2*)(k0p + t * 8 + oc);
            dl[t][0] -= k2.x; dl[t][1] -= k2.y;
            dl[t][2] -= k2.x; dl[t][3] -= k2.y;
            mlo = fmaxf(mlo, fmaxf(dl[t][0], dl[t][1]));
            mhi = fmaxf(mhi, fmaxf(dl[t][2], dl[t][3]));
        }
#pragma unroll
        for (int off = 1; off < 4; off <<= 1) {
            mlo = fmaxf(mlo, __shfl_xor_sync(0xffffffffu, mlo, off));
            mhi = fmaxf(mhi, __shfl_xor_sync(0xffffffffu, mhi, off));
        }
        float slo = 0.f, shi = 0.f;
#pragma unroll
        for (int t = 0; t < 16; ++t) {
            dl[t][0] = __expf(dl[t][0] - mlo); dl[t][1] = __expf(dl[t][1] - mlo);
            dl[t][2] = __expf(dl[t][2] - mhi); dl[t][3] = __expf(dl[t][3] - mhi);
            slo += dl[t][0] + dl[t][1];
            shi += dl[t][2] + dl[t][3];
        }
#pragma unroll
        for (int off = 1; off < 4; off <<= 1) {
            slo += __shfl_xor_sync(0xffffffffu, slo, off);
            shi += __shfl_xor_sync(0xffffffffu, shi, off);
        }
        float ilo = 1.f / slo, ihi = 1.f / shi;
        int rlo = w16 + (lane >> 2), rhi = rlo + 8;
        float* sFR = (float*)(smem + SM_FR);
#pragma unroll
        for (int t = 0; t < 16; ++t) {
            float2 flo = make_float2(dl[t][0] * ilo, dl[t][1] * ilo);
            float2 fhi = make_float2(dl[t][2] * ihi, dl[t][3] * ihi);
            *(float2*)(sFR + rlo * N_R + t * 8 + oc) = flo;
            *(float2*)(sFR + rhi * N_R + t * 8 + oc) = fhi;
            *(float2*)(frs + (size_t)(bBase + rlo) * N_R + t * 8 + oc) = flo;
            *(float2*)(frs + (size_t)(bBase + rhi) * N_R + t * 8 + oc) = fhi;
        }
    }
    __syncthreads();

    // ---- main loop: warp grid 2m x 2n; sync-free (named pair barriers)
    int mq = wid >> 1, nq = wid & 1;
    int rm = mq * 32, nb = nq * 64;

    uint32_t aF[2][4][4];
#pragma unroll
    for (int mt = 0; mt < 2; ++mt)
#pragma unroll
        for (int ks = 0; ks < 4; ++ks) {
            uint32_t offA = SWZ((unsigned)((rm + mt * 16 + lrow) * 128 + ks * 32 + lcol));
            LDSM4(aF[mt][ks], sb + SM_XH + offA);
        }
    // B offsets are half-local (rows 0..63 within this nq's 8KB region)
    uint32_t offB16[16];
#pragma unroll
    for (int ks = 0; ks < 4; ++ks)
#pragma unroll
        for (int tp = 0; tp < 4; ++tp)
            offB16[ks * 4 + tp] =
                SWZ((unsigned)((tp * 16 + lrow) * 128 + ks * 32 + lcol));

    uint32_t myB0 = sb + SM_B + nq * 16384;       // [buf] = myB0 + buf*8192
    const char* gQuarter = (const char*)g_Bf + nq * 8192 + mq * 4096 + lane * 16;

    float acc[4][4][2];
#pragma unroll
    for (int a = 0; a < 4; ++a)
#pragma unroll
        for (int b = 0; b < 4; ++b) acc[a][b][0] = acc[a][b][1] = 0.f;

    const float* wfs = (const float*)(smem + SM_WF);
    const float* sFR = (const float*)(smem + SM_FR);
    int barid = nq + 1;

    for (int c = 0; c < N_CHUNK; ++c) {
        int cur = c & 1, nxt = cur ^ 1;

        CP_WAIT0();                 // my quarter of chunk c landed
        BAR_PAIR(barid);            // partner landed + done reading buf nxt

        if (c + 1 < N_CHUNK) {      // stage my quarter of chunk c+1
            const char* src = gQuarter + (c + 1) * 16384;
            uint32_t dst = myB0 + nxt * 8192 + mq * 4096 + lane * 16;
#pragma unroll
            for (int t = 0; t < 8; ++t) cp16(dst + t * 512, src + t * 512);
        }
        CP_COMMIT();

        float2 f2[2][2];
#pragma unroll
        for (int mt = 0; mt < 2; ++mt)
#pragma unroll
            for (int h = 0; h < 2; ++h) {
                int row = rm + mt * 16 + (lane >> 2) + h * 8;
                f2[mt][h] = *(const float2*)(sFR + row * N_R + c * RC + nq * 2);
            }

        float d[2][4][2][4];
#pragma unroll
        for (int tp = 0; tp < 4; ++tp)
#pragma unroll
            for (int n8 = 0; n8 < 2; ++n8) {
                int rule = tp >> 1;
                int o0 = ((tp & 1) << 4) + (n8 << 3) + oc;
                float2 wf = *(const float2*)(wfs + (c * RC + nq * 2 + rule) * OUT_D + o0);
#pragma unroll
                for (int mt = 0; mt < 2; ++mt) {
                    d[mt][tp][n8][0] = wf.x; d[mt][tp][n8][1] = wf.y;
                    d[mt][tp][n8][2] = wf.x; d[mt][tp][n8][3] = wf.y;
                }
            }

        uint32_t bufB = myB0 + cur * 8192;
#pragma unroll
        for (int ks = 0; ks < 4; ++ks) {
#pragma unroll
            for (int tp = 0; tp < 4; ++tp) {
                uint32_t bH[4];
                LDSM4(bH, bufB + offB16[ks * 4 + tp]);
#pragma unroll
                for (int mt = 0; mt < 2; ++mt) {
                    MMA(d[mt][tp][0], aF[mt][ks], bH[0], bH[2]);
                    MMA(d[mt][tp][1], aF[mt][ks], bH[1], bH[3]);
                }
            }
        }

#pragma unroll
        for (int mt = 0; mt < 2; ++mt)
#pragma unroll
            for (int tp = 0; tp < 4; ++tp)
#pragma unroll
                for (int n8 = 0; n8 < 2; ++n8) {
                    int rq = tp >> 1;
                    int op = ((tp & 1) << 1) + n8;
#pragma unroll
                    for (int h = 0; h < 2; ++h) {
                        float fl = rq ? f2[mt][h].y : f2[mt][h].x;
                        acc[mt * 2 + h][op][0] = fmaf(fl, d[mt][tp][n8][2 * h],     acc[mt * 2 + h][op][0]);
                        acc[mt * 2 + h][op][1] = fmaf(fl, d[mt][tp][n8][2 * h + 1], acc[mt * 2 + h][op][1]);
                    }
                }
    }

    // ---- epilogue: reduce nq pair via smem (T_xh region dead), + bias, store
    __syncthreads();
    float* red = (float*)smem;            // [64][32] fp32 = 8 KB
    if (nq == 1) {
#pragma unroll
        for (int mt = 0; mt < 2; ++mt)
#pragma unroll
            for (int h = 0; h < 2; ++h) {
                int row = rm + mt * 16 + (lane >> 2) + h * 8;
#pragma unroll
                for (int op = 0; op < 4; ++op)
                    *(float2*)(red + row * 32 + op * 8 + oc) =
                        make_float2(acc[mt * 2 + h][op][0], acc[mt * 2 + h][op][1]);
            }
    }
    __syncthreads();
    if (nq == 0) {
        float2 b2[4];
#pragma unroll
        for (int op = 0; op < 4; ++op)
            b2[op] = *(const float2*)(bias + op * 8 + oc);
#pragma unroll
        for (int mt = 0; mt < 2; ++mt)
#pragma unroll
            for (int h = 0; h < 2; ++h) {
                int row = rm + mt * 16 + (lane >> 2) + h * 8;
#pragma unroll
                for (int op = 0; op < 4; ++op) {
                    float2 r2 = *(const float2*)(red + row * 32 + op * 8 + oc);
                    float2 v = make_float2(acc[mt * 2 + h][op][0] + r2.x + b2[op].x,
                                           acc[mt * 2 + h][op][1] + r2.y + b2[op].y);
                    *(float2*)(out + (size_t)(bBase + row) * OUT_D + op * 8 + oc) = v;
                }
            }
    }
}

// ---------------- launch --------------------------------------------------
extern "C" void kernel_launch(void* const* d_in, const int* in_sizes, int n_in,
                              void* d_out, int out_size) {
    const float* X       = (const float*)d_in[0];
    const float* centers = (const float*)d_in[1];
    const float* sigmas  = (const float*)d_in[2];
    const float* W       = (const float*)d_in[3];
    const float* bias    = (const float*)d_in[4];

    float* out = (float*)d_out;
    float* frs = out + (size_t)B_TOT * OUT_D;

    cudaFuncSetAttribute(kfused, cudaFuncAttributeMaxDynamicSharedMemorySize,
                         SMEM_TOTAL);

    prep_all<<<720, 256>>>(W, centers, sigmas);
    kfused<<<B_TOT / M_CTA, 128, SMEM_TOTAL>>>(X, bias, out, frs);
}